// round 1
// baseline (speedup 1.0000x reference)
#include <cuda_runtime.h>
#include <cuda_bf16.h>
#include <math.h>

// Problem constants
#define BB 2
#define SS 2048
#define DD 1024
#define HH 16
#define HDD 64
#define MM (BB*SS)          // 4096 rows
#define FF (4*DD)           // 4096 mlp hidden

// ---------------- scratch (device globals; no allocation allowed) ----------------
__device__ float g_q [MM*DD];
__device__ float g_k [MM*DD];
__device__ float g_v [MM*DD];
__device__ float g_y [MM*DD];
__device__ float g_x1[MM*DD];
__device__ float g_h [MM*DD];
__device__ float g_m [MM*FF];
__device__ float g_x2[MM*DD];

// ---------------- helpers ----------------
__device__ __forceinline__ float gelu_tanh_f(float x) {
    float x3 = x * x * x;
    float t = tanhf(0.7978845608028654f * (x + 0.044715f * x3));
    return 0.5f * x * (1.0f + t);
}

// ---------------- generic SGEMM: C = A[MxK] @ W[KxN] + bias, epilogue ----------------
// EPI: 0 = bias only, 1 = bias + GELU, 2 = bias + residual R
template <int EPI>
__global__ __launch_bounds__(256, 2)
void sgemm_kernel(const float* __restrict__ A, const float* __restrict__ W,
                  const float* __restrict__ bias, const float* __restrict__ R,
                  float* __restrict__ C, int M, int N, int K) {
    constexpr int BM = 128, BN = 128, BK = 16, TM = 8, TN = 8;
    __shared__ float As[BK][BM];
    __shared__ float Bs[BK][BN];

    const int tid = threadIdx.x;            // 0..255
    const int tr = tid >> 4;                // 0..15
    const int tc = tid & 15;                // 0..15
    const int rowBase = blockIdx.y * BM;
    const int colBase = blockIdx.x * BN;

    float acc[TM][TN];
#pragma unroll
    for (int i = 0; i < TM; i++)
#pragma unroll
        for (int j = 0; j < TN; j++) acc[i][j] = 0.0f;

    for (int k0 = 0; k0 < K; k0 += BK) {
        // Load A tile (BM x BK) transposed, B tile (BK x BN), 2 float4 each per thread.
#pragma unroll
        for (int i = 0; i < 2; i++) {
            int u = tid + i * 256;          // 0..511
            int ar  = u >> 2;               // 0..127
            int ac4 = u & 3;                // 0..3
            float4 av = *reinterpret_cast<const float4*>(
                &A[(size_t)(rowBase + ar) * K + k0 + ac4 * 4]);
            As[ac4 * 4 + 0][ar] = av.x;
            As[ac4 * 4 + 1][ar] = av.y;
            As[ac4 * 4 + 2][ar] = av.z;
            As[ac4 * 4 + 3][ar] = av.w;
            int br  = u >> 5;               // 0..15
            int bc4 = u & 31;               // 0..31
            *reinterpret_cast<float4*>(&Bs[br][bc4 * 4]) =
                *reinterpret_cast<const float4*>(
                    &W[(size_t)(k0 + br) * N + colBase + bc4 * 4]);
        }
        __syncthreads();

#pragma unroll
        for (int k = 0; k < BK; k++) {
            float a[TM], b[TN];
            float4 a0 = *reinterpret_cast<const float4*>(&As[k][tr * TM]);
            float4 a1 = *reinterpret_cast<const float4*>(&As[k][tr * TM + 4]);
            a[0]=a0.x; a[1]=a0.y; a[2]=a0.z; a[3]=a0.w;
            a[4]=a1.x; a[5]=a1.y; a[6]=a1.z; a[7]=a1.w;
            float4 b0 = *reinterpret_cast<const float4*>(&Bs[k][tc * TN]);
            float4 b1 = *reinterpret_cast<const float4*>(&Bs[k][tc * TN + 4]);
            b[0]=b0.x; b[1]=b0.y; b[2]=b0.z; b[3]=b0.w;
            b[4]=b1.x; b[5]=b1.y; b[6]=b1.z; b[7]=b1.w;
#pragma unroll
            for (int i = 0; i < TM; i++)
#pragma unroll
                for (int j = 0; j < TN; j++)
                    acc[i][j] = fmaf(a[i], b[j], acc[i][j]);
        }
        __syncthreads();
    }

    // Epilogue
#pragma unroll
    for (int i = 0; i < TM; i++) {
        int row = rowBase + tr * TM + i;
#pragma unroll
        for (int j = 0; j < TN; j += 4) {
            int col = colBase + tc * TN + j;
            float4 o;
            o.x = acc[i][j + 0] + bias[col + 0];
            o.y = acc[i][j + 1] + bias[col + 1];
            o.z = acc[i][j + 2] + bias[col + 2];
            o.w = acc[i][j + 3] + bias[col + 3];
            if (EPI == 1) {
                o.x = gelu_tanh_f(o.x); o.y = gelu_tanh_f(o.y);
                o.z = gelu_tanh_f(o.z); o.w = gelu_tanh_f(o.w);
            }
            if (EPI == 2) {
                float4 r4 = *reinterpret_cast<const float4*>(&R[(size_t)row * N + col]);
                o.x += r4.x; o.y += r4.y; o.z += r4.z; o.w += r4.w;
            }
            *reinterpret_cast<float4*>(&C[(size_t)row * N + col]) = o;
        }
    }
}

// ---------------- flash-style causal attention (fp32) ----------------
// 1 thread = 1 query row; block = 128 query rows for one (b,h).
// K/V tiles of 32 keys in smem; per-tile two-pass online softmax.
#define BQ 128
#define BKk 32

__global__ __launch_bounds__(128, 3)
void flash_kernel(const float* __restrict__ Q, const float* __restrict__ Kg,
                  const float* __restrict__ Vg, float* __restrict__ O) {
    __shared__ float Ks[BKk][HDD];
    __shared__ float Vs[BKk][HDD];
    __shared__ float Sc[BQ][BKk + 1];

    const int qt  = gridDim.x - 1 - blockIdx.x;   // heavy tiles first
    const int h   = blockIdx.y;
    const int b   = blockIdx.z;
    const int tid = threadIdx.x;
    const int iq  = qt * BQ + tid;

    const float* qrow = Q + ((size_t)(b * SS + iq)) * DD + h * HDD;
    float4 q4[16];
#pragma unroll
    for (int i = 0; i < 16; i++) q4[i] = reinterpret_cast<const float4*>(qrow)[i];

    float acc[HDD];
#pragma unroll
    for (int d = 0; d < HDD; d++) acc[d] = 0.0f;
    float m = -1e30f, l = 0.0f;
    const float scale = 0.125f; // 1/sqrt(64)

    const float* kbase = Kg + ((size_t)b * SS) * DD + h * HDD;
    const float* vbase = Vg + ((size_t)b * SS) * DD + h * HDD;

    const int nkt = (qt + 1) * (BQ / BKk);
    for (int kt = 0; kt < nkt; kt++) {
        // cooperative tile load: 512 float4 per tensor, 128 threads -> 4 each
#pragma unroll
        for (int i = 0; i < 4; i++) {
            int u  = tid + i * 128;
            int r  = u >> 4;
            int c4 = u & 15;
            reinterpret_cast<float4*>(&Ks[r][0])[c4] =
                reinterpret_cast<const float4*>(kbase + (size_t)(kt * BKk + r) * DD)[c4];
            reinterpret_cast<float4*>(&Vs[r][0])[c4] =
                reinterpret_cast<const float4*>(vbase + (size_t)(kt * BKk + r) * DD)[c4];
        }
        __syncthreads();

        // pass 1: scores + tile max
        float tmax = -1e30f;
#pragma unroll 4
        for (int kk = 0; kk < BKk; kk++) {
            const float4* kr = reinterpret_cast<const float4*>(&Ks[kk][0]);
            float s = 0.0f;
#pragma unroll
            for (int i = 0; i < 16; i++) {
                float4 kv = kr[i];
                s = fmaf(q4[i].x, kv.x, s);
                s = fmaf(q4[i].y, kv.y, s);
                s = fmaf(q4[i].z, kv.z, s);
                s = fmaf(q4[i].w, kv.w, s);
            }
            s *= scale;
            if (kt * BKk + kk > iq) s = -1e30f;
            Sc[tid][kk] = s;
            tmax = fmaxf(tmax, s);
        }

        // merge running max once per tile
        float mnew = fmaxf(m, tmax);
        float corr = __expf(m - mnew);
        l *= corr;
#pragma unroll
        for (int d = 0; d < HDD; d++) acc[d] *= corr;
        m = mnew;

        // pass 2: weighted V accumulation
#pragma unroll 2
        for (int kk = 0; kk < BKk; kk++) {
            float p = __expf(Sc[tid][kk] - m);
            l += p;
            const float4* vr = reinterpret_cast<const float4*>(&Vs[kk][0]);
#pragma unroll
            for (int i = 0; i < 16; i++) {
                float4 vv = vr[i];
                acc[i * 4 + 0] = fmaf(p, vv.x, acc[i * 4 + 0]);
                acc[i * 4 + 1] = fmaf(p, vv.y, acc[i * 4 + 1]);
                acc[i * 4 + 2] = fmaf(p, vv.z, acc[i * 4 + 2]);
                acc[i * 4 + 3] = fmaf(p, vv.w, acc[i * 4 + 3]);
            }
        }
        __syncthreads();
    }

    float inv = 1.0f / l;
    float* orow = O + ((size_t)(b * SS + iq)) * DD + h * HDD;
#pragma unroll
    for (int i = 0; i < 16; i++) {
        float4 o4 = make_float4(acc[i*4+0]*inv, acc[i*4+1]*inv,
                                acc[i*4+2]*inv, acc[i*4+3]*inv);
        reinterpret_cast<float4*>(orow)[i] = o4;
    }
}

// ---------------- LayerNorm over last dim (1024), one block per row ----------------
__global__ __launch_bounds__(256)
void ln_kernel(const float* __restrict__ in, const float* __restrict__ gamma,
               const float* __restrict__ beta, float* __restrict__ out) {
    __shared__ float red1[8];
    __shared__ float red2[8];
    const int row = blockIdx.x;
    const int tid = threadIdx.x; // 256 threads * 4 = 1024
    float4 v = reinterpret_cast<const float4*>(in + (size_t)row * DD)[tid];

    float s = v.x + v.y + v.z + v.w;
#pragma unroll
    for (int o = 16; o > 0; o >>= 1) s += __shfl_xor_sync(0xffffffffu, s, o);
    if ((tid & 31) == 0) red1[tid >> 5] = s;
    __syncthreads();
    float mean = (red1[0]+red1[1]+red1[2]+red1[3]+red1[4]+red1[5]+red1[6]+red1[7])
                 * (1.0f / 1024.0f);

    float dx = v.x - mean, dy = v.y - mean, dz = v.z - mean, dw = v.w - mean;
    float sq = dx*dx + dy*dy + dz*dz + dw*dw;
#pragma unroll
    for (int o = 16; o > 0; o >>= 1) sq += __shfl_xor_sync(0xffffffffu, sq, o);
    if ((tid & 31) == 0) red2[tid >> 5] = sq;
    __syncthreads();
    float var = (red2[0]+red2[1]+red2[2]+red2[3]+red2[4]+red2[5]+red2[6]+red2[7])
                * (1.0f / 1024.0f);
    float r = rsqrtf(var + 1e-5f);

    float4 g4 = reinterpret_cast<const float4*>(gamma)[tid];
    float4 b4 = reinterpret_cast<const float4*>(beta)[tid];
    float4 o4;
    o4.x = dx * r * g4.x + b4.x;
    o4.y = dy * r * g4.y + b4.y;
    o4.z = dz * r * g4.z + b4.z;
    o4.w = dw * r * g4.w + b4.w;
    reinterpret_cast<float4*>(out + (size_t)row * DD)[tid] = o4;
}

// ---------------- launch ----------------
extern "C" void kernel_launch(void* const* d_in, const int* in_sizes, int n_in,
                              void* d_out, int out_size) {
    const float* x     = (const float*)d_in[0];
    const float* Wq    = (const float*)d_in[1];
    const float* bq    = (const float*)d_in[2];
    const float* Wk    = (const float*)d_in[3];
    const float* bk    = (const float*)d_in[4];
    const float* Wv    = (const float*)d_in[5];
    const float* bv    = (const float*)d_in[6];
    const float* Wp    = (const float*)d_in[7];
    const float* bp    = (const float*)d_in[8];
    const float* g0    = (const float*)d_in[9];
    const float* beta0 = (const float*)d_in[10];
    const float* W1    = (const float*)d_in[11];
    const float* b1    = (const float*)d_in[12];
    const float* W2    = (const float*)d_in[13];
    const float* b2    = (const float*)d_in[14];
    const float* g1    = (const float*)d_in[15];
    const float* beta1 = (const float*)d_in[16];
    float* out = (float*)d_out;

    float *q, *k, *v, *y, *x1, *hbuf, *mbuf, *x2;
    cudaGetSymbolAddress((void**)&q,    g_q);
    cudaGetSymbolAddress((void**)&k,    g_k);
    cudaGetSymbolAddress((void**)&v,    g_v);
    cudaGetSymbolAddress((void**)&y,    g_y);
    cudaGetSymbolAddress((void**)&x1,   g_x1);
    cudaGetSymbolAddress((void**)&hbuf, g_h);
    cudaGetSymbolAddress((void**)&mbuf, g_m);
    cudaGetSymbolAddress((void**)&x2,   g_x2);

    dim3 gProj(DD / 128, MM / 128);   // (8, 32)
    dim3 gMlp1(FF / 128, MM / 128);   // (32, 32)

    // QKV projections
    sgemm_kernel<0><<<gProj, 256>>>(x, Wq, bq, nullptr, q, MM, DD, DD);
    sgemm_kernel<0><<<gProj, 256>>>(x, Wk, bk, nullptr, k, MM, DD, DD);
    sgemm_kernel<0><<<gProj, 256>>>(x, Wv, bv, nullptr, v, MM, DD, DD);

    // causal attention
    flash_kernel<<<dim3(SS / BQ, HH, BB), 128>>>(q, k, v, y);

    // out-proj + residual:  x1 = y@Wp + bp + x
    sgemm_kernel<2><<<gProj, 256>>>(y, Wp, bp, x, x1, MM, DD, DD);

    // LN0
    ln_kernel<<<MM, 256>>>(x1, g0, beta0, hbuf);

    // MLP:  m = gelu(h@W1 + b1);  x2 = m@W2 + b2 + x1
    sgemm_kernel<1><<<gMlp1, 256>>>(hbuf, W1, b1, nullptr, mbuf, MM, FF, DD);
    sgemm_kernel<2><<<gProj, 256>>>(mbuf, W2, b2, x1, x2, MM, DD, FF);

    // LN1 -> output
    ln_kernel<<<MM, 256>>>(x2, g1, beta1, out);
}

// round 3
// speedup vs baseline: 1.7282x; 1.7282x over previous
#include <cuda_runtime.h>
#include <cuda_bf16.h>
#include <math.h>
#include <cstdint>

// Problem constants
#define BB 2
#define SS 2048
#define DD 1024
#define HH 16
#define HDD 64
#define MM (BB*SS)          // 4096 rows
#define FF (4*DD)           // 4096 mlp hidden
#define QKVN 3072

// ---------------- scratch (device globals; no allocation allowed) ----------------
__device__ float g_wt [12u*1024u*1024u];        // transposed+rounded weights
__device__ float g_qkv[(size_t)MM*QKVN];        // fused q|k|v
__device__ float g_y  [MM*DD];
__device__ float g_x1 [MM*DD];
__device__ float g_h  [MM*DD];
__device__ float g_m  [(size_t)MM*FF];
__device__ float g_x2 [MM*DD];
__device__ float g_bqkv[QKVN];

// ---------------- helpers ----------------
__device__ __forceinline__ uint32_t smem_u32(const void* p) {
    uint32_t a;
    asm("{ .reg .u64 t; cvta.to.shared.u64 t, %1; cvt.u32.u64 %0, t; }" : "=r"(a) : "l"(p));
    return a;
}
__device__ __forceinline__ uint32_t f2tf32(float x) {
    uint32_t u;
    asm("cvt.rna.tf32.f32 %0, %1;" : "=r"(u) : "f"(x));
    return u;
}
__device__ __forceinline__ float gelu_tanh_f(float x) {
    float x3 = x * x * x;
    float t = tanhf(0.7978845608028654f * (x + 0.044715f * x3));
    return 0.5f * x * (1.0f + t);
}

#define CP_ASYNC16(dst, src) \
    asm volatile("cp.async.cg.shared.global [%0], [%1], 16;" :: "r"(dst), "l"(src))
#define CP_COMMIT() asm volatile("cp.async.commit_group;" ::: "memory")
#define CP_WAIT2()  asm volatile("cp.async.wait_group 2;" ::: "memory")

__device__ __forceinline__ void mma_tf32(float* c, const uint32_t* a, const uint32_t* b) {
    asm volatile(
        "mma.sync.aligned.m16n8k8.row.col.f32.tf32.tf32.f32 "
        "{%0,%1,%2,%3}, {%4,%5,%6,%7}, {%8,%9}, {%0,%1,%2,%3};"
        : "+f"(c[0]), "+f"(c[1]), "+f"(c[2]), "+f"(c[3])
        : "r"(a[0]), "r"(a[1]), "r"(a[2]), "r"(a[3]), "r"(b[0]), "r"(b[1]));
}

// ---------------- prep: transpose + tf32-round weights: out[n*K+k] = rna(in[k*N+n]) ----------------
__global__ __launch_bounds__(256)
void transpose_rna_kernel(const float* __restrict__ in, float* __restrict__ out, int K, int N) {
    __shared__ float t[32][33];
    int n0 = blockIdx.x * 32, k0 = blockIdx.y * 32;
    int tx = threadIdx.x & 31, ty = threadIdx.x >> 5;
#pragma unroll
    for (int i = 0; i < 4; i++)
        t[ty + i * 8][tx] = in[(size_t)(k0 + ty + i * 8) * N + n0 + tx];
    __syncthreads();
#pragma unroll
    for (int i = 0; i < 4; i++)
        out[(size_t)(n0 + ty + i * 8) * K + k0 + tx] =
            __uint_as_float(f2tf32(t[tx][ty + i * 8]));
}

__global__ void concat_bias_kernel(const float* bq, const float* bk, const float* bv, float* o) {
    int c = threadIdx.x;
    o[blockIdx.x * 1024 + c] =
        (blockIdx.x == 0) ? bq[c] : (blockIdx.x == 1) ? bk[c] : bv[c];
}

// ---------------- tf32 mma.sync GEMM: C[M,N] = A[M,K] @ Wt[N,K]^T + bias (+epi) ----------------
// EPI: 0 = bias, 1 = bias+GELU, 2 = bias+residual
#define GBM 128
#define GBN 128
#define GBK 32
#define APAD 36                         // padded float stride per row
#define TILE_BYTES (128 * APAD * 4)     // 18432 per operand tile
#define STG_BYTES  (2 * TILE_BYTES)     // 36864 per stage
#define NSTG 3
#define SM_BIAS 0
#define SM_STAGES 512
#define SM_TOTAL (SM_STAGES + NSTG * STG_BYTES)   // 111104 bytes

template <int EPI>
__global__ __launch_bounds__(256, 1)
void tc_gemm(const float* __restrict__ A, const float* __restrict__ Wt,
             const float* __restrict__ bias, const float* __restrict__ R,
             float* __restrict__ C, int M, int N, int K) {
    extern __shared__ char smem[];
    const uint32_t sb = smem_u32(smem);
    const int tid  = threadIdx.x;
    const int wid  = tid >> 5, lane = tid & 31;
    const int warpM = wid >> 2;          // 0..1
    const int warpN = wid & 3;           // 0..3
    const int gid = lane >> 2;           // group id 0..7
    const int tig = lane & 3;            // thread in group 0..3
    const int rowBase = blockIdx.y * GBM;
    const int colBase = blockIdx.x * GBN;

    // stage bias tile (128 floats)
    if (tid < 32)
        *reinterpret_cast<float4*>(smem + SM_BIAS + tid * 16) =
            *reinterpret_cast<const float4*>(bias + colBase + tid * 4);

    const float* Abase = A  + (size_t)rowBase * K;
    const float* Bbase = Wt + (size_t)colBase * K;
    const int nch = K >> 5;

    // prologue: issue up to 3 stages
#pragma unroll
    for (int s = 0; s < NSTG; s++) {
        if (s < nch) {
            const uint32_t st = sb + SM_STAGES + s * STG_BYTES;
#pragma unroll
            for (int i = 0; i < 4; i++) {
                int u = tid + i * 256;
                int r = u >> 3, c4 = u & 7;
                CP_ASYNC16(st + (uint32_t)(r * APAD + c4 * 4) * 4,
                           Abase + (size_t)r * K + s * GBK + c4 * 4);
                CP_ASYNC16(st + TILE_BYTES + (uint32_t)(r * APAD + c4 * 4) * 4,
                           Bbase + (size_t)r * K + s * GBK + c4 * 4);
            }
        }
        CP_COMMIT();
    }

    float acc[4][4][4];
#pragma unroll
    for (int mt = 0; mt < 4; mt++)
#pragma unroll
        for (int nt = 0; nt < 4; nt++)
#pragma unroll
            for (int rr = 0; rr < 4; rr++) acc[mt][nt][rr] = 0.0f;

    for (int c = 0; c < nch; c++) {
        CP_WAIT2();
        __syncthreads();
        const int slot = c % NSTG;
        const float* As = reinterpret_cast<const float*>(smem + SM_STAGES + slot * STG_BYTES);
        const float* Bs = As + TILE_BYTES / 4;

#pragma unroll
        for (int ks = 0; ks < 4; ks++) {
            const int k0 = ks * 8 + tig;
            uint32_t a[4][4], b[4][2];
#pragma unroll
            for (int mt = 0; mt < 4; mt++) {
                int r0 = warpM * 64 + mt * 16 + gid;
                a[mt][0] = f2tf32(As[r0 * APAD + k0]);
                a[mt][1] = f2tf32(As[(r0 + 8) * APAD + k0]);
                a[mt][2] = f2tf32(As[r0 * APAD + k0 + 4]);
                a[mt][3] = f2tf32(As[(r0 + 8) * APAD + k0 + 4]);
            }
#pragma unroll
            for (int nt = 0; nt < 4; nt++) {
                int n0 = warpN * 32 + nt * 8 + gid;
                b[nt][0] = __float_as_uint(Bs[n0 * APAD + k0]);
                b[nt][1] = __float_as_uint(Bs[n0 * APAD + k0 + 4]);
            }
#pragma unroll
            for (int mt = 0; mt < 4; mt++)
#pragma unroll
                for (int nt = 0; nt < 4; nt++)
                    mma_tf32(acc[mt][nt], a[mt], b[nt]);
        }
        __syncthreads();

        // refill the slot we just freed
        if (c + NSTG < nch) {
            const uint32_t st = sb + SM_STAGES + slot * STG_BYTES;
            const int cc = c + NSTG;
#pragma unroll
            for (int i = 0; i < 4; i++) {
                int u = tid + i * 256;
                int r = u >> 3, c4 = u & 7;
                CP_ASYNC16(st + (uint32_t)(r * APAD + c4 * 4) * 4,
                           Abase + (size_t)r * K + cc * GBK + c4 * 4);
                CP_ASYNC16(st + TILE_BYTES + (uint32_t)(r * APAD + c4 * 4) * 4,
                           Bbase + (size_t)r * K + cc * GBK + c4 * 4);
            }
        }
        CP_COMMIT();
    }

    // epilogue
    const float* bs = reinterpret_cast<const float*>(smem + SM_BIAS);
#pragma unroll
    for (int mt = 0; mt < 4; mt++) {
        int r0 = rowBase + warpM * 64 + mt * 16 + gid;
#pragma unroll
        for (int nt = 0; nt < 4; nt++) {
            int colL = warpN * 32 + nt * 8 + 2 * tig;
            int col  = colBase + colL;
            float b0 = bs[colL], b1 = bs[colL + 1];
            float2 o0 = make_float2(acc[mt][nt][0] + b0, acc[mt][nt][1] + b1);
            float2 o1 = make_float2(acc[mt][nt][2] + b0, acc[mt][nt][3] + b1);
            if (EPI == 1) {
                o0.x = gelu_tanh_f(o0.x); o0.y = gelu_tanh_f(o0.y);
                o1.x = gelu_tanh_f(o1.x); o1.y = gelu_tanh_f(o1.y);
            }
            if (EPI == 2) {
                float2 r0v = *reinterpret_cast<const float2*>(R + (size_t)r0 * N + col);
                float2 r1v = *reinterpret_cast<const float2*>(R + (size_t)(r0 + 8) * N + col);
                o0.x += r0v.x; o0.y += r0v.y;
                o1.x += r1v.x; o1.y += r1v.y;
            }
            *reinterpret_cast<float2*>(C + (size_t)r0 * N + col) = o0;
            *reinterpret_cast<float2*>(C + (size_t)(r0 + 8) * N + col) = o1;
        }
    }
}

// ---------------- flash-style causal attention (fp32), reads fused qkv ----------------
#define BQ 128
#define BKk 32

__global__ __launch_bounds__(128, 3)
void flash_kernel(const float* __restrict__ QKV, float* __restrict__ O) {
    __shared__ float Ks[BKk][HDD];
    __shared__ float Vs[BKk][HDD];
    __shared__ float Sc[BQ][BKk + 1];

    const int qt  = gridDim.x - 1 - blockIdx.x;   // heavy tiles first
    const int h   = blockIdx.y;
    const int b   = blockIdx.z;
    const int tid = threadIdx.x;
    const int iq  = qt * BQ + tid;

    const float* qrow = QKV + ((size_t)(b * SS + iq)) * QKVN + h * HDD;
    float4 q4[16];
#pragma unroll
    for (int i = 0; i < 16; i++) q4[i] = reinterpret_cast<const float4*>(qrow)[i];

    float acc[HDD];
#pragma unroll
    for (int d = 0; d < HDD; d++) acc[d] = 0.0f;
    float m = -1e30f, l = 0.0f;
    const float scale = 0.125f;

    const float* kbase = QKV + ((size_t)(b * SS)) * QKVN + DD + h * HDD;
    const float* vbase = QKV + ((size_t)(b * SS)) * QKVN + 2 * DD + h * HDD;

    const int nkt = (qt + 1) * (BQ / BKk);
    for (int kt = 0; kt < nkt; kt++) {
#pragma unroll
        for (int i = 0; i < 4; i++) {
            int u  = tid + i * 128;
            int r  = u >> 4;
            int c4 = u & 15;
            reinterpret_cast<float4*>(&Ks[r][0])[c4] =
                reinterpret_cast<const float4*>(kbase + (size_t)(kt * BKk + r) * QKVN)[c4];
            reinterpret_cast<float4*>(&Vs[r][0])[c4] =
                reinterpret_cast<const float4*>(vbase + (size_t)(kt * BKk + r) * QKVN)[c4];
        }
        __syncthreads();

        float tmax = -1e30f;
#pragma unroll 4
        for (int kk = 0; kk < BKk; kk++) {
            const float4* kr = reinterpret_cast<const float4*>(&Ks[kk][0]);
            float s = 0.0f;
#pragma unroll
            for (int i = 0; i < 16; i++) {
                float4 kv = kr[i];
                s = fmaf(q4[i].x, kv.x, s);
                s = fmaf(q4[i].y, kv.y, s);
                s = fmaf(q4[i].z, kv.z, s);
                s = fmaf(q4[i].w, kv.w, s);
            }
            s *= scale;
            if (kt * BKk + kk > iq) s = -1e30f;
            Sc[tid][kk] = s;
            tmax = fmaxf(tmax, s);
        }

        float mnew = fmaxf(m, tmax);
        float corr = __expf(m - mnew);
        l *= corr;
#pragma unroll
        for (int d = 0; d < HDD; d++) acc[d] *= corr;
        m = mnew;

#pragma unroll 2
        for (int kk = 0; kk < BKk; kk++) {
            float p = __expf(Sc[tid][kk] - m);
            l += p;
            const float4* vr = reinterpret_cast<const float4*>(&Vs[kk][0]);
#pragma unroll
            for (int i = 0; i < 16; i++) {
                float4 vv = vr[i];
                acc[i * 4 + 0] = fmaf(p, vv.x, acc[i * 4 + 0]);
                acc[i * 4 + 1] = fmaf(p, vv.y, acc[i * 4 + 1]);
                acc[i * 4 + 2] = fmaf(p, vv.z, acc[i * 4 + 2]);
                acc[i * 4 + 3] = fmaf(p, vv.w, acc[i * 4 + 3]);
            }
        }
        __syncthreads();
    }

    float inv = 1.0f / l;
    float* orow = O + ((size_t)(b * SS + iq)) * DD + h * HDD;
#pragma unroll
    for (int i = 0; i < 16; i++) {
        float4 o4 = make_float4(acc[i*4+0]*inv, acc[i*4+1]*inv,
                                acc[i*4+2]*inv, acc[i*4+3]*inv);
        reinterpret_cast<float4*>(orow)[i] = o4;
    }
}

// ---------------- LayerNorm ----------------
__global__ __launch_bounds__(256)
void ln_kernel(const float* __restrict__ in, const float* __restrict__ gamma,
               const float* __restrict__ beta, float* __restrict__ out) {
    __shared__ float red1[8];
    __shared__ float red2[8];
    const int row = blockIdx.x;
    const int tid = threadIdx.x;
    float4 v = reinterpret_cast<const float4*>(in + (size_t)row * DD)[tid];

    float s = v.x + v.y + v.z + v.w;
#pragma unroll
    for (int o = 16; o > 0; o >>= 1) s += __shfl_xor_sync(0xffffffffu, s, o);
    if ((tid & 31) == 0) red1[tid >> 5] = s;
    __syncthreads();
    float mean = (red1[0]+red1[1]+red1[2]+red1[3]+red1[4]+red1[5]+red1[6]+red1[7])
                 * (1.0f / 1024.0f);

    float dx = v.x - mean, dy = v.y - mean, dz = v.z - mean, dw = v.w - mean;
    float sq = dx*dx + dy*dy + dz*dz + dw*dw;
#pragma unroll
    for (int o = 16; o > 0; o >>= 1) sq += __shfl_xor_sync(0xffffffffu, sq, o);
    if ((tid & 31) == 0) red2[tid >> 5] = sq;
    __syncthreads();
    float var = (red2[0]+red2[1]+red2[2]+red2[3]+red2[4]+red2[5]+red2[6]+red2[7])
                * (1.0f / 1024.0f);
    float r = rsqrtf(var + 1e-5f);

    float4 g4 = reinterpret_cast<const float4*>(gamma)[tid];
    float4 b4 = reinterpret_cast<const float4*>(beta)[tid];
    float4 o4;
    o4.x = dx * r * g4.x + b4.x;
    o4.y = dy * r * g4.y + b4.y;
    o4.z = dz * r * g4.z + b4.z;
    o4.w = dw * r * g4.w + b4.w;
    reinterpret_cast<float4*>(out + (size_t)row * DD)[tid] = o4;
}

// ---------------- launch ----------------
extern "C" void kernel_launch(void* const* d_in, const int* in_sizes, int n_in,
                              void* d_out, int out_size) {
    const float* x     = (const float*)d_in[0];
    const float* Wq    = (const float*)d_in[1];
    const float* bq    = (const float*)d_in[2];
    const float* Wk    = (const float*)d_in[3];
    const float* bk    = (const float*)d_in[4];
    const float* Wv    = (const float*)d_in[5];
    const float* bv    = (const float*)d_in[6];
    const float* Wp    = (const float*)d_in[7];
    const float* bp    = (const float*)d_in[8];
    const float* g0    = (const float*)d_in[9];
    const float* beta0 = (const float*)d_in[10];
    const float* W1    = (const float*)d_in[11];
    const float* b1    = (const float*)d_in[12];
    const float* W2    = (const float*)d_in[13];
    const float* b2    = (const float*)d_in[14];
    const float* g1    = (const float*)d_in[15];
    const float* beta1 = (const float*)d_in[16];
    float* out = (float*)d_out;

    float *wt, *qkv, *y, *x1, *hbuf, *mbuf, *x2, *bqkv;
    cudaGetSymbolAddress((void**)&wt,   g_wt);
    cudaGetSymbolAddress((void**)&qkv,  g_qkv);
    cudaGetSymbolAddress((void**)&y,    g_y);
    cudaGetSymbolAddress((void**)&x1,   g_x1);
    cudaGetSymbolAddress((void**)&hbuf, g_h);
    cudaGetSymbolAddress((void**)&mbuf, g_m);
    cudaGetSymbolAddress((void**)&x2,   g_x2);
    cudaGetSymbolAddress((void**)&bqkv, g_bqkv);

    float* WtQKV = wt;                       // [3072][1024]
    float* WtP   = wt + 3u*1024u*1024u;      // [1024][1024]
    float* WtM1  = wt + 4u*1024u*1024u;      // [4096][1024]
    float* WtM2  = wt + 8u*1024u*1024u;      // [1024][4096]

    cudaFuncSetAttribute(tc_gemm<0>, cudaFuncAttributeMaxDynamicSharedMemorySize, SM_TOTAL);
    cudaFuncSetAttribute(tc_gemm<1>, cudaFuncAttributeMaxDynamicSharedMemorySize, SM_TOTAL);
    cudaFuncSetAttribute(tc_gemm<2>, cudaFuncAttributeMaxDynamicSharedMemorySize, SM_TOTAL);

    // prep: transposes + rounding + bias concat
    transpose_rna_kernel<<<dim3(32, 32),  256>>>(Wq, WtQKV,                 DD, DD);
    transpose_rna_kernel<<<dim3(32, 32),  256>>>(Wk, WtQKV + 1024u*1024u,   DD, DD);
    transpose_rna_kernel<<<dim3(32, 32),  256>>>(Wv, WtQKV + 2u*1024u*1024u,DD, DD);
    transpose_rna_kernel<<<dim3(32, 32),  256>>>(Wp, WtP,                   DD, DD);
    transpose_rna_kernel<<<dim3(128, 32), 256>>>(W1, WtM1,                  DD, FF);
    transpose_rna_kernel<<<dim3(32, 128), 256>>>(W2, WtM2,                  FF, DD);
    concat_bias_kernel<<<3, 1024>>>(bq, bk, bv, bqkv);

    // qkv = x @ [Wq|Wk|Wv] + bqkv
    tc_gemm<0><<<dim3(QKVN/GBN, MM/GBM), 256, SM_TOTAL>>>(x, WtQKV, bqkv, nullptr, qkv, MM, QKVN, DD);

    // causal attention
    flash_kernel<<<dim3(SS / BQ, HH, BB), 128>>>(qkv, y);

    // x1 = y@Wp + bp + x
    tc_gemm<2><<<dim3(DD/GBN, MM/GBM), 256, SM_TOTAL>>>(y, WtP, bp, x, x1, MM, DD, DD);

    // LN0
    ln_kernel<<<MM, 256>>>(x1, g0, beta0, hbuf);

    // MLP
    tc_gemm<1><<<dim3(FF/GBN, MM/GBM), 256, SM_TOTAL>>>(hbuf, WtM1, b1, nullptr, mbuf, MM, FF, DD);
    tc_gemm<2><<<dim3(DD/GBN, MM/GBM), 256, SM_TOTAL>>>(mbuf, WtM2, b2, x1, x2, MM, DD, FF);

    // LN1 -> output
    ln_kernel<<<MM, 256>>>(x2, g1, beta1, out);
}

// round 4
// speedup vs baseline: 1.9706x; 1.1403x over previous
#include <cuda_runtime.h>
#include <cuda_bf16.h>
#include <math.h>
#include <cstdint>

// Problem constants
#define BB 2
#define SS 2048
#define DD 1024
#define HH 16
#define HDD 64
#define MM (BB*SS)          // 4096 rows
#define FF (4*DD)           // 4096 mlp hidden
#define QKVN 3072

// ---------------- scratch (device globals; no allocation allowed) ----------------
__device__ float g_wt [12u*1024u*1024u];        // transposed+rounded weights
__device__ float g_qkv[(size_t)MM*QKVN];        // fused q|k|v
__device__ float g_y  [MM*DD];
__device__ float g_x1 [MM*DD];
__device__ float g_h  [MM*DD];
__device__ float g_m  [(size_t)MM*FF];
__device__ float g_x2 [MM*DD];
__device__ float g_bqkv[QKVN];

// ---------------- helpers ----------------
__device__ __forceinline__ uint32_t smem_u32(const void* p) {
    uint32_t a;
    asm("{ .reg .u64 t; cvta.to.shared.u64 t, %1; cvt.u32.u64 %0, t; }" : "=r"(a) : "l"(p));
    return a;
}
__device__ __forceinline__ uint32_t f2tf32(float x) {
    uint32_t u;
    asm("cvt.rna.tf32.f32 %0, %1;" : "=r"(u) : "f"(x));
    return u;
}
__device__ __forceinline__ float gelu_tanh_f(float x) {
    float x3 = x * x * x;
    float t = tanhf(0.7978845608028654f * (x + 0.044715f * x3));
    return 0.5f * x * (1.0f + t);
}

#define CP_ASYNC16(dst, src) \
    asm volatile("cp.async.cg.shared.global [%0], [%1], 16;" :: "r"(dst), "l"(src))
#define CP_COMMIT() asm volatile("cp.async.commit_group;" ::: "memory")
#define CP_WAIT2()  asm volatile("cp.async.wait_group 2;" ::: "memory")

__device__ __forceinline__ void mma_tf32(float* c, const uint32_t* a, const uint32_t* b) {
    asm volatile(
        "mma.sync.aligned.m16n8k8.row.col.f32.tf32.tf32.f32 "
        "{%0,%1,%2,%3}, {%4,%5,%6,%7}, {%8,%9}, {%0,%1,%2,%3};"
        : "+f"(c[0]), "+f"(c[1]), "+f"(c[2]), "+f"(c[3])
        : "r"(a[0]), "r"(a[1]), "r"(a[2]), "r"(a[3]), "r"(b[0]), "r"(b[1]));
}
__device__ __forceinline__ void ldsm_x4(uint32_t& r0, uint32_t& r1, uint32_t& r2, uint32_t& r3,
                                        uint32_t addr) {
    asm volatile("ldmatrix.sync.aligned.m8n8.x4.shared.b16 {%0,%1,%2,%3}, [%4];"
        : "=r"(r0), "=r"(r1), "=r"(r2), "=r"(r3) : "r"(addr));
}

// ---------------- prep: transpose + tf32-round weights: out[n*K+k] = rna(in[k*N+n]) ----------------
__global__ __launch_bounds__(256)
void transpose_rna_kernel(const float* __restrict__ in, float* __restrict__ out, int K, int N) {
    __shared__ float t[32][33];
    int n0 = blockIdx.x * 32, k0 = blockIdx.y * 32;
    int tx = threadIdx.x & 31, ty = threadIdx.x >> 5;
#pragma unroll
    for (int i = 0; i < 4; i++)
        t[ty + i * 8][tx] = in[(size_t)(k0 + ty + i * 8) * N + n0 + tx];
    __syncthreads();
#pragma unroll
    for (int i = 0; i < 4; i++)
        out[(size_t)(n0 + ty + i * 8) * K + k0 + tx] =
            __uint_as_float(f2tf32(t[tx][ty + i * 8]));
}

__global__ void concat_bias_kernel(const float* bq, const float* bk, const float* bv, float* o) {
    int c = threadIdx.x;
    o[blockIdx.x * 1024 + c] =
        (blockIdx.x == 0) ? bq[c] : (blockIdx.x == 1) ? bk[c] : bv[c];
}

// ---------------- tf32 mma.sync GEMM with ldmatrix fragments ----------------
// C[M,N] = A[M,K] @ Wt[N,K]^T + bias (+epi);  EPI: 0=bias, 1=bias+GELU, 2=bias+residual
#define GBM 128
#define GBN 128
#define GBK 32
#define APAD 36                         // padded float stride per row
#define TILE_BYTES (128 * APAD * 4)     // 18432 per operand tile
#define STG_BYTES  (2 * TILE_BYTES)     // 36864 per stage
#define NSTG 3
#define SM_BIAS 0
#define SM_STAGES 512
#define SM_TOTAL (SM_STAGES + NSTG * STG_BYTES)   // 111104 bytes

template <int EPI>
__global__ __launch_bounds__(256, 1)
void tc_gemm(const float* __restrict__ A, const float* __restrict__ Wt,
             const float* __restrict__ bias, const float* __restrict__ R,
             float* __restrict__ C, int M, int N, int K) {
    extern __shared__ char smem[];
    const uint32_t sb = smem_u32(smem);
    const int tid  = threadIdx.x;
    const int wid  = tid >> 5, lane = tid & 31;
    const int warpM = wid >> 2;          // 0..1
    const int warpN = wid & 3;           // 0..3
    const int gid = lane >> 2;           // group id 0..7
    const int tig = lane & 3;            // thread in group 0..3
    const int rowBase = blockIdx.y * GBM;
    const int colBase = blockIdx.x * GBN;

    // per-lane ldmatrix byte offsets (relative to operand tile start)
    const uint32_t rowA = (uint32_t)(warpM * 64 + (lane & 7) + ((lane & 8) ? 8 : 0));
    const uint32_t colA = (lane & 16) ? 4u : 0u;
    const uint32_t aoff_l = (rowA * APAD + colA) * 4u;
    const uint32_t rowB = (uint32_t)(warpN * 32 + ((lane & 16) ? 8 : 0) + (lane & 7));
    const uint32_t colB = (lane & 8) ? 4u : 0u;
    const uint32_t boff_l = (rowB * APAD + colB) * 4u;

    // stage bias tile (128 floats)
    if (tid < 32)
        *reinterpret_cast<float4*>(smem + SM_BIAS + tid * 16) =
            *reinterpret_cast<const float4*>(bias + colBase + tid * 4);

    const float* Abase = A  + (size_t)rowBase * K;
    const float* Bbase = Wt + (size_t)colBase * K;
    const int nch = K >> 5;

    // prologue: issue up to 3 stages
#pragma unroll
    for (int s = 0; s < NSTG; s++) {
        if (s < nch) {
            const uint32_t st = sb + SM_STAGES + s * STG_BYTES;
#pragma unroll
            for (int i = 0; i < 4; i++) {
                int u = tid + i * 256;
                int r = u >> 3, c4 = u & 7;
                CP_ASYNC16(st + (uint32_t)(r * APAD + c4 * 4) * 4,
                           Abase + (size_t)r * K + s * GBK + c4 * 4);
                CP_ASYNC16(st + TILE_BYTES + (uint32_t)(r * APAD + c4 * 4) * 4,
                           Bbase + (size_t)r * K + s * GBK + c4 * 4);
            }
        }
        CP_COMMIT();
    }

    float acc[4][4][4];
#pragma unroll
    for (int mt = 0; mt < 4; mt++)
#pragma unroll
        for (int nt = 0; nt < 4; nt++)
#pragma unroll
            for (int rr = 0; rr < 4; rr++) acc[mt][nt][rr] = 0.0f;

    for (int c = 0; c < nch; c++) {
        CP_WAIT2();
        __syncthreads();
        const int slot = c % NSTG;
        const uint32_t abase = sb + SM_STAGES + slot * STG_BYTES + aoff_l;
        const uint32_t bbase = sb + SM_STAGES + slot * STG_BYTES + TILE_BYTES + boff_l;

#pragma unroll
        for (int ks = 0; ks < 4; ks++) {
            const uint32_t kb = (uint32_t)(ks * 32);     // ks*8 floats
            uint32_t a[4][4], b[4][2];
#pragma unroll
            for (int mt = 0; mt < 4; mt++)
                ldsm_x4(a[mt][0], a[mt][1], a[mt][2], a[mt][3],
                        abase + (uint32_t)(mt * 16 * APAD * 4) + kb);
#pragma unroll
            for (int p = 0; p < 2; p++)
                ldsm_x4(b[2*p][0], b[2*p][1], b[2*p+1][0], b[2*p+1][1],
                        bbase + (uint32_t)(p * 16 * APAD * 4) + kb);
#pragma unroll
            for (int mt = 0; mt < 4; mt++)
#pragma unroll
                for (int nt = 0; nt < 4; nt++)
                    mma_tf32(acc[mt][nt], a[mt], b[nt]);
        }
        __syncthreads();

        // refill the slot we just freed
        if (c + NSTG < nch) {
            const uint32_t st = sb + SM_STAGES + slot * STG_BYTES;
            const int cc = c + NSTG;
#pragma unroll
            for (int i = 0; i < 4; i++) {
                int u = tid + i * 256;
                int r = u >> 3, c4 = u & 7;
                CP_ASYNC16(st + (uint32_t)(r * APAD + c4 * 4) * 4,
                           Abase + (size_t)r * K + cc * GBK + c4 * 4);
                CP_ASYNC16(st + TILE_BYTES + (uint32_t)(r * APAD + c4 * 4) * 4,
                           Bbase + (size_t)r * K + cc * GBK + c4 * 4);
            }
        }
        CP_COMMIT();
    }

    // epilogue
    const float* bs = reinterpret_cast<const float*>(smem + SM_BIAS);
#pragma unroll
    for (int mt = 0; mt < 4; mt++) {
        int r0 = rowBase + warpM * 64 + mt * 16 + gid;
#pragma unroll
        for (int nt = 0; nt < 4; nt++) {
            int colL = warpN * 32 + nt * 8 + 2 * tig;
            int col  = colBase + colL;
            float b0 = bs[colL], b1 = bs[colL + 1];
            float2 o0 = make_float2(acc[mt][nt][0] + b0, acc[mt][nt][1] + b1);
            float2 o1 = make_float2(acc[mt][nt][2] + b0, acc[mt][nt][3] + b1);
            if (EPI == 1) {
                o0.x = gelu_tanh_f(o0.x); o0.y = gelu_tanh_f(o0.y);
                o1.x = gelu_tanh_f(o1.x); o1.y = gelu_tanh_f(o1.y);
            }
            if (EPI == 2) {
                float2 r0v = *reinterpret_cast<const float2*>(R + (size_t)r0 * N + col);
                float2 r1v = *reinterpret_cast<const float2*>(R + (size_t)(r0 + 8) * N + col);
                o0.x += r0v.x; o0.y += r0v.y;
                o1.x += r1v.x; o1.y += r1v.y;
            }
            *reinterpret_cast<float2*>(C + (size_t)r0 * N + col) = o0;
            *reinterpret_cast<float2*>(C + (size_t)(r0 + 8) * N + col) = o1;
        }
    }
}

// ---------------- flash-style causal attention (fp32), scores in registers ----------------
#define BQ 128
#define BK2 16

__global__ __launch_bounds__(128, 3)
void flash_kernel(const float* __restrict__ QKV, float* __restrict__ O) {
    __shared__ float Ks[BK2][HDD];
    __shared__ float Vs[BK2][HDD];

    const int qt  = gridDim.x - 1 - blockIdx.x;   // heavy tiles first
    const int h   = blockIdx.y;
    const int b   = blockIdx.z;
    const int tid = threadIdx.x;
    const int iq  = qt * BQ + tid;

    const float* qrow = QKV + ((size_t)(b * SS + iq)) * QKVN + h * HDD;
    float4 q4[16];
#pragma unroll
    for (int i = 0; i < 16; i++) q4[i] = reinterpret_cast<const float4*>(qrow)[i];

    float acc[HDD];
#pragma unroll
    for (int d = 0; d < HDD; d++) acc[d] = 0.0f;
    float m = -1e30f, l = 0.0f;
    const float scale = 0.125f;

    const float* kbase = QKV + ((size_t)(b * SS)) * QKVN + DD + h * HDD;
    const float* vbase = QKV + ((size_t)(b * SS)) * QKVN + 2 * DD + h * HDD;

    const int nkt = (qt + 1) * (BQ / BK2);
    for (int kt = 0; kt < nkt; kt++) {
        // cooperative tile load: 256 float4 per tensor, 128 threads -> 2 each
#pragma unroll
        for (int i = 0; i < 2; i++) {
            int u  = tid + i * 128;
            int r  = u >> 4;
            int c4 = u & 15;
            reinterpret_cast<float4*>(&Ks[r][0])[c4] =
                reinterpret_cast<const float4*>(kbase + (size_t)(kt * BK2 + r) * QKVN)[c4];
            reinterpret_cast<float4*>(&Vs[r][0])[c4] =
                reinterpret_cast<const float4*>(vbase + (size_t)(kt * BK2 + r) * QKVN)[c4];
        }
        __syncthreads();

        // scores for 16 keys, kept in registers
        float s[BK2];
        float tmax = -1e30f;
#pragma unroll
        for (int kk = 0; kk < BK2; kk++) {
            const float4* kr = reinterpret_cast<const float4*>(&Ks[kk][0]);
            float sv = 0.0f;
#pragma unroll
            for (int i = 0; i < 16; i++) {
                float4 kv = kr[i];
                sv = fmaf(q4[i].x, kv.x, sv);
                sv = fmaf(q4[i].y, kv.y, sv);
                sv = fmaf(q4[i].z, kv.z, sv);
                sv = fmaf(q4[i].w, kv.w, sv);
            }
            sv *= scale;
            if (kt * BK2 + kk > iq) sv = -1e30f;
            s[kk] = sv;
            tmax = fmaxf(tmax, sv);
        }

        float mnew = fmaxf(m, tmax);
        float corr = __expf(m - mnew);
        l *= corr;
#pragma unroll
        for (int d = 0; d < HDD; d++) acc[d] *= corr;
        m = mnew;

#pragma unroll
        for (int kk = 0; kk < BK2; kk++) {
            float p = __expf(s[kk] - m);
            l += p;
            const float4* vr = reinterpret_cast<const float4*>(&Vs[kk][0]);
#pragma unroll
            for (int i = 0; i < 16; i++) {
                float4 vv = vr[i];
                acc[i * 4 + 0] = fmaf(p, vv.x, acc[i * 4 + 0]);
                acc[i * 4 + 1] = fmaf(p, vv.y, acc[i * 4 + 1]);
                acc[i * 4 + 2] = fmaf(p, vv.z, acc[i * 4 + 2]);
                acc[i * 4 + 3] = fmaf(p, vv.w, acc[i * 4 + 3]);
            }
        }
        __syncthreads();
    }

    float inv = 1.0f / l;
    float* orow = O + ((size_t)(b * SS + iq)) * DD + h * HDD;
#pragma unroll
    for (int i = 0; i < 16; i++) {
        float4 o4 = make_float4(acc[i*4+0]*inv, acc[i*4+1]*inv,
                                acc[i*4+2]*inv, acc[i*4+3]*inv);
        reinterpret_cast<float4*>(orow)[i] = o4;
    }
}

// ---------------- LayerNorm ----------------
__global__ __launch_bounds__(256)
void ln_kernel(const float* __restrict__ in, const float* __restrict__ gamma,
               const float* __restrict__ beta, float* __restrict__ out) {
    __shared__ float red1[8];
    __shared__ float red2[8];
    const int row = blockIdx.x;
    const int tid = threadIdx.x;
    float4 v = reinterpret_cast<const float4*>(in + (size_t)row * DD)[tid];

    float s = v.x + v.y + v.z + v.w;
#pragma unroll
    for (int o = 16; o > 0; o >>= 1) s += __shfl_xor_sync(0xffffffffu, s, o);
    if ((tid & 31) == 0) red1[tid >> 5] = s;
    __syncthreads();
    float mean = (red1[0]+red1[1]+red1[2]+red1[3]+red1[4]+red1[5]+red1[6]+red1[7])
                 * (1.0f / 1024.0f);

    float dx = v.x - mean, dy = v.y - mean, dz = v.z - mean, dw = v.w - mean;
    float sq = dx*dx + dy*dy + dz*dz + dw*dw;
#pragma unroll
    for (int o = 16; o > 0; o >>= 1) sq += __shfl_xor_sync(0xffffffffu, sq, o);
    if ((tid & 31) == 0) red2[tid >> 5] = sq;
    __syncthreads();
    float var = (red2[0]+red2[1]+red2[2]+red2[3]+red2[4]+red2[5]+red2[6]+red2[7])
                * (1.0f / 1024.0f);
    float r = rsqrtf(var + 1e-5f);

    float4 g4 = reinterpret_cast<const float4*>(gamma)[tid];
    float4 b4 = reinterpret_cast<const float4*>(beta)[tid];
    float4 o4;
    o4.x = dx * r * g4.x + b4.x;
    o4.y = dy * r * g4.y + b4.y;
    o4.z = dz * r * g4.z + b4.z;
    o4.w = dw * r * g4.w + b4.w;
    reinterpret_cast<float4*>(out + (size_t)row * DD)[tid] = o4;
}

// ---------------- launch ----------------
extern "C" void kernel_launch(void* const* d_in, const int* in_sizes, int n_in,
                              void* d_out, int out_size) {
    const float* x     = (const float*)d_in[0];
    const float* Wq    = (const float*)d_in[1];
    const float* bq    = (const float*)d_in[2];
    const float* Wk    = (const float*)d_in[3];
    const float* bk    = (const float*)d_in[4];
    const float* Wv    = (const float*)d_in[5];
    const float* bv    = (const float*)d_in[6];
    const float* Wp    = (const float*)d_in[7];
    const float* bp    = (const float*)d_in[8];
    const float* g0    = (const float*)d_in[9];
    const float* beta0 = (const float*)d_in[10];
    const float* W1    = (const float*)d_in[11];
    const float* b1    = (const float*)d_in[12];
    const float* W2    = (const float*)d_in[13];
    const float* b2    = (const float*)d_in[14];
    const float* g1    = (const float*)d_in[15];
    const float* beta1 = (const float*)d_in[16];
    float* out = (float*)d_out;

    float *wt, *qkv, *y, *x1, *hbuf, *mbuf, *x2, *bqkv;
    cudaGetSymbolAddress((void**)&wt,   g_wt);
    cudaGetSymbolAddress((void**)&qkv,  g_qkv);
    cudaGetSymbolAddress((void**)&y,    g_y);
    cudaGetSymbolAddress((void**)&x1,   g_x1);
    cudaGetSymbolAddress((void**)&hbuf, g_h);
    cudaGetSymbolAddress((void**)&mbuf, g_m);
    cudaGetSymbolAddress((void**)&x2,   g_x2);
    cudaGetSymbolAddress((void**)&bqkv, g_bqkv);

    float* WtQKV = wt;                       // [3072][1024]
    float* WtP   = wt + 3u*1024u*1024u;      // [1024][1024]
    float* WtM1  = wt + 4u*1024u*1024u;      // [4096][1024]
    float* WtM2  = wt + 8u*1024u*1024u;      // [1024][4096]

    cudaFuncSetAttribute(tc_gemm<0>, cudaFuncAttributeMaxDynamicSharedMemorySize, SM_TOTAL);
    cudaFuncSetAttribute(tc_gemm<1>, cudaFuncAttributeMaxDynamicSharedMemorySize, SM_TOTAL);
    cudaFuncSetAttribute(tc_gemm<2>, cudaFuncAttributeMaxDynamicSharedMemorySize, SM_TOTAL);

    // prep: transposes + rounding + bias concat
    transpose_rna_kernel<<<dim3(32, 32),  256>>>(Wq, WtQKV,                 DD, DD);
    transpose_rna_kernel<<<dim3(32, 32),  256>>>(Wk, WtQKV + 1024u*1024u,   DD, DD);
    transpose_rna_kernel<<<dim3(32, 32),  256>>>(Wv, WtQKV + 2u*1024u*1024u,DD, DD);
    transpose_rna_kernel<<<dim3(32, 32),  256>>>(Wp, WtP,                   DD, DD);
    transpose_rna_kernel<<<dim3(128, 32), 256>>>(W1, WtM1,                  DD, FF);
    transpose_rna_kernel<<<dim3(32, 128), 256>>>(W2, WtM2,                  FF, DD);
    concat_bias_kernel<<<3, 1024>>>(bq, bk, bv, bqkv);

    // qkv = x @ [Wq|Wk|Wv] + bqkv
    tc_gemm<0><<<dim3(QKVN/GBN, MM/GBM), 256, SM_TOTAL>>>(x, WtQKV, bqkv, nullptr, qkv, MM, QKVN, DD);

    // causal attention
    flash_kernel<<<dim3(SS / BQ, HH, BB), 128>>>(qkv, y);

    // x1 = y@Wp + bp + x
    tc_gemm<2><<<dim3(DD/GBN, MM/GBM), 256, SM_TOTAL>>>(y, WtP, bp, x, x1, MM, DD, DD);

    // LN0
    ln_kernel<<<MM, 256>>>(x1, g0, beta0, hbuf);

    // MLP
    tc_gemm<1><<<dim3(FF/GBN, MM/GBM), 256, SM_TOTAL>>>(hbuf, WtM1, b1, nullptr, mbuf, MM, FF, DD);
    tc_gemm<2><<<dim3(DD/GBN, MM/GBM), 256, SM_TOTAL>>>(mbuf, WtM2, b2, x1, x2, MM, DD, FF);

    // LN1 -> output
    ln_kernel<<<MM, 256>>>(x2, g1, beta1, out);
}

// round 5
// speedup vs baseline: 3.4714x; 1.7616x over previous
#include <cuda_runtime.h>
#include <cuda_bf16.h>
#include <math.h>
#include <cstdint>

// Problem constants
#define BB 2
#define SS 2048
#define DD 1024
#define HH 16
#define HDD 64
#define MM (BB*SS)          // 4096 rows
#define FF (4*DD)           // 4096 mlp hidden
#define QKVN 3072

// ---------------- scratch (device globals; no allocation allowed) ----------------
__device__ float g_wt [12u*1024u*1024u];        // transposed+rounded weights
__device__ float g_qkv[(size_t)MM*QKVN];        // fused q|k|v
__device__ float g_y  [MM*DD];
__device__ float g_x1 [MM*DD];
__device__ float g_h  [MM*DD];
__device__ float g_m  [(size_t)MM*FF];
__device__ float g_x2 [MM*DD];
__device__ float g_bqkv[QKVN];

// ---------------- helpers ----------------
__device__ __forceinline__ uint32_t smem_u32(const void* p) {
    uint32_t a;
    asm("{ .reg .u64 t; cvta.to.shared.u64 t, %1; cvt.u32.u64 %0, t; }" : "=r"(a) : "l"(p));
    return a;
}
__device__ __forceinline__ uint32_t f2tf32(float x) {
    uint32_t u;
    asm("cvt.rna.tf32.f32 %0, %1;" : "=r"(u) : "f"(x));
    return u;
}
__device__ __forceinline__ uint32_t pack_bf16(float lo, float hi) {
    uint32_t d;
    asm("cvt.rn.bf16x2.f32 %0, %1, %2;" : "=r"(d) : "f"(hi), "f"(lo));
    return d;
}
__device__ __forceinline__ float gelu_tanh_f(float x) {
    float x3 = x * x * x;
    float t = tanhf(0.7978845608028654f * (x + 0.044715f * x3));
    return 0.5f * x * (1.0f + t);
}

#define CP_ASYNC16(dst, src) \
    asm volatile("cp.async.cg.shared.global [%0], [%1], 16;" :: "r"(dst), "l"(src))
#define CP_COMMIT() asm volatile("cp.async.commit_group;" ::: "memory")
#define CP_WAIT2()  asm volatile("cp.async.wait_group 2;" ::: "memory")

__device__ __forceinline__ void mma_tf32(float* c, const uint32_t* a, const uint32_t* b) {
    asm volatile(
        "mma.sync.aligned.m16n8k8.row.col.f32.tf32.tf32.f32 "
        "{%0,%1,%2,%3}, {%4,%5,%6,%7}, {%8,%9}, {%0,%1,%2,%3};"
        : "+f"(c[0]), "+f"(c[1]), "+f"(c[2]), "+f"(c[3])
        : "r"(a[0]), "r"(a[1]), "r"(a[2]), "r"(a[3]), "r"(b[0]), "r"(b[1]));
}
__device__ __forceinline__ void mma_bf16(float* c, const uint32_t* a, uint32_t b0, uint32_t b1) {
    asm volatile(
        "mma.sync.aligned.m16n8k16.row.col.f32.bf16.bf16.f32 "
        "{%0,%1,%2,%3}, {%4,%5,%6,%7}, {%8,%9}, {%0,%1,%2,%3};"
        : "+f"(c[0]), "+f"(c[1]), "+f"(c[2]), "+f"(c[3])
        : "r"(a[0]), "r"(a[1]), "r"(a[2]), "r"(a[3]), "r"(b0), "r"(b1));
}
__device__ __forceinline__ void ldsm_x4(uint32_t& r0, uint32_t& r1, uint32_t& r2, uint32_t& r3,
                                        uint32_t addr) {
    asm volatile("ldmatrix.sync.aligned.m8n8.x4.shared.b16 {%0,%1,%2,%3}, [%4];"
        : "=r"(r0), "=r"(r1), "=r"(r2), "=r"(r3) : "r"(addr));
}
__device__ __forceinline__ void ldsm_x4_t(uint32_t& r0, uint32_t& r1, uint32_t& r2, uint32_t& r3,
                                          uint32_t addr) {
    asm volatile("ldmatrix.sync.aligned.m8n8.x4.trans.shared.b16 {%0,%1,%2,%3}, [%4];"
        : "=r"(r0), "=r"(r1), "=r"(r2), "=r"(r3) : "r"(addr));
}

// ---------------- prep: transpose + tf32-round weights ----------------
__global__ __launch_bounds__(256)
void transpose_rna_kernel(const float* __restrict__ in, float* __restrict__ out, int K, int N) {
    __shared__ float t[32][33];
    int n0 = blockIdx.x * 32, k0 = blockIdx.y * 32;
    int tx = threadIdx.x & 31, ty = threadIdx.x >> 5;
#pragma unroll
    for (int i = 0; i < 4; i++)
        t[ty + i * 8][tx] = in[(size_t)(k0 + ty + i * 8) * N + n0 + tx];
    __syncthreads();
#pragma unroll
    for (int i = 0; i < 4; i++)
        out[(size_t)(n0 + ty + i * 8) * K + k0 + tx] =
            __uint_as_float(f2tf32(t[tx][ty + i * 8]));
}

__global__ void concat_bias_kernel(const float* bq, const float* bk, const float* bv, float* o) {
    int c = threadIdx.x;
    o[blockIdx.x * 1024 + c] =
        (blockIdx.x == 0) ? bq[c] : (blockIdx.x == 1) ? bk[c] : bv[c];
}

// ---------------- tf32 mma.sync GEMM with ldmatrix fragments ----------------
// C[M,N] = A[M,K] @ Wt[N,K]^T + bias (+epi);  EPI: 0=bias, 1=bias+GELU, 2=bias+residual
// NB: CTA tile N (128 or 256). CTA M = 128, 8 warps, warp tile 64 x (NB/4).
#define GBM 128
#define GBK 32
#define APAD 36
#define NSTG 3
#define SM_STAGES 1024

template <int EPI, int NB>
__global__ __launch_bounds__(256, 1)
void tc_gemm(const float* __restrict__ A, const float* __restrict__ Wt,
             const float* __restrict__ bias, const float* __restrict__ R,
             float* __restrict__ C, int M, int N, int K) {
    constexpr int WN = NB / 4;                 // warp n extent (32 or 64)
    constexpr int NT = WN / 8;                 // n-tiles per warp (4 or 8)
    constexpr int NP = WN / 16;                // ldsm B pairs (2 or 4)
    constexpr int ATB = GBM * APAD * 4;        // A tile bytes 18432
    constexpr int BTB = NB * APAD * 4;         // B tile bytes
    constexpr int STGB = ATB + BTB;

    extern __shared__ char smem[];
    const uint32_t sb = smem_u32(smem);
    const int tid  = threadIdx.x;
    const int wid  = tid >> 5, lane = tid & 31;
    const int warpM = wid >> 2;          // 0..1
    const int warpN = wid & 3;           // 0..3
    const int gid = lane >> 2;
    const int tig = lane & 3;
    const int rowBase = blockIdx.y * GBM;
    const int colBase = blockIdx.x * NB;

    // per-lane ldmatrix byte offsets (relative to operand tile start)
    const uint32_t aoff_l = ((uint32_t)(warpM * 64 + (lane & 15)) * APAD +
                             ((lane & 16) ? 4u : 0u)) * 4u;
    const uint32_t boff_l = ((uint32_t)(warpN * WN + ((lane & 16) ? 8 : 0) + (lane & 7)) * APAD +
                             ((lane & 8) ? 4u : 0u)) * 4u;

    // stage bias tile (NB floats)
    if (tid < NB / 4)
        *reinterpret_cast<float4*>(smem + tid * 16) =
            *reinterpret_cast<const float4*>(bias + colBase + tid * 4);

    const float* Abase = A  + (size_t)rowBase * K;
    const float* Bbase = Wt + (size_t)colBase * K;
    const int nch = K >> 5;

    // prologue
#pragma unroll
    for (int s = 0; s < NSTG; s++) {
        if (s < nch) {
            const uint32_t st = sb + SM_STAGES + s * STGB;
#pragma unroll
            for (int i = 0; i < 4; i++) {            // A: 1024 float4
                int u = tid + i * 256;
                int r = u >> 3, c4 = u & 7;
                CP_ASYNC16(st + (uint32_t)(r * APAD + c4 * 4) * 4,
                           Abase + (size_t)r * K + s * GBK + c4 * 4);
            }
#pragma unroll
            for (int i = 0; i < NB / 32; i++) {      // B: NB*8 float4
                int u = tid + i * 256;
                int r = u >> 3, c4 = u & 7;
                CP_ASYNC16(st + ATB + (uint32_t)(r * APAD + c4 * 4) * 4,
                           Bbase + (size_t)r * K + s * GBK + c4 * 4);
            }
        }
        CP_COMMIT();
    }

    float acc[4][NT][4];
#pragma unroll
    for (int mt = 0; mt < 4; mt++)
#pragma unroll
        for (int nt = 0; nt < NT; nt++)
#pragma unroll
            for (int rr = 0; rr < 4; rr++) acc[mt][nt][rr] = 0.0f;

    for (int c = 0; c < nch; c++) {
        CP_WAIT2();
        __syncthreads();
        const int slot = c % NSTG;
        const uint32_t abase = sb + SM_STAGES + slot * STGB + aoff_l;
        const uint32_t bbase = sb + SM_STAGES + slot * STGB + ATB + boff_l;

#pragma unroll
        for (int ks = 0; ks < 4; ks++) {
            const uint32_t kb = (uint32_t)(ks * 32);
            uint32_t a[4][4], b[NT][2];
#pragma unroll
            for (int mt = 0; mt < 4; mt++)
                ldsm_x4(a[mt][0], a[mt][1], a[mt][2], a[mt][3],
                        abase + (uint32_t)(mt * 16 * APAD * 4) + kb);
#pragma unroll
            for (int p = 0; p < NP; p++)
                ldsm_x4(b[2*p][0], b[2*p][1], b[2*p+1][0], b[2*p+1][1],
                        bbase + (uint32_t)(p * 16 * APAD * 4) + kb);
#pragma unroll
            for (int mt = 0; mt < 4; mt++)
#pragma unroll
                for (int nt = 0; nt < NT; nt++)
                    mma_tf32(acc[mt][nt], a[mt], b[nt]);
        }
        __syncthreads();

        if (c + NSTG < nch) {
            const uint32_t st = sb + SM_STAGES + slot * STGB;
            const int cc = c + NSTG;
#pragma unroll
            for (int i = 0; i < 4; i++) {
                int u = tid + i * 256;
                int r = u >> 3, c4 = u & 7;
                CP_ASYNC16(st + (uint32_t)(r * APAD + c4 * 4) * 4,
                           Abase + (size_t)r * K + cc * GBK + c4 * 4);
            }
#pragma unroll
            for (int i = 0; i < NB / 32; i++) {
                int u = tid + i * 256;
                int r = u >> 3, c4 = u & 7;
                CP_ASYNC16(st + ATB + (uint32_t)(r * APAD + c4 * 4) * 4,
                           Bbase + (size_t)r * K + cc * GBK + c4 * 4);
            }
        }
        CP_COMMIT();
    }

    // epilogue
    const float* bs = reinterpret_cast<const float*>(smem);
#pragma unroll
    for (int mt = 0; mt < 4; mt++) {
        int r0 = rowBase + warpM * 64 + mt * 16 + gid;
#pragma unroll
        for (int nt = 0; nt < NT; nt++) {
            int colL = warpN * WN + nt * 8 + 2 * tig;
            int col  = colBase + colL;
            float b0 = bs[colL], b1 = bs[colL + 1];
            float2 o0 = make_float2(acc[mt][nt][0] + b0, acc[mt][nt][1] + b1);
            float2 o1 = make_float2(acc[mt][nt][2] + b0, acc[mt][nt][3] + b1);
            if (EPI == 1) {
                o0.x = gelu_tanh_f(o0.x); o0.y = gelu_tanh_f(o0.y);
                o1.x = gelu_tanh_f(o1.x); o1.y = gelu_tanh_f(o1.y);
            }
            if (EPI == 2) {
                float2 r0v = *reinterpret_cast<const float2*>(R + (size_t)r0 * N + col);
                float2 r1v = *reinterpret_cast<const float2*>(R + (size_t)(r0 + 8) * N + col);
                o0.x += r0v.x; o0.y += r0v.y;
                o1.x += r1v.x; o1.y += r1v.y;
            }
            *reinterpret_cast<float2*>(C + (size_t)r0 * N + col) = o0;
            *reinterpret_cast<float2*>(C + (size_t)(r0 + 8) * N + col) = o1;
        }
    }
}

// ---------------- tensor-core flash attention (bf16 mma, fp32 softmax) ----------------
// CTA: 64 q-rows (4 warps x 16), K/V tiles of 64. Qs/Ks: [64 rows][hd], Vs: [64 keys][hd],
// all bf16 with row stride 72 (pad 8).
#define FPAD 72

__global__ __launch_bounds__(128)
void flash_kernel(const float* __restrict__ QKV, float* __restrict__ O) {
    __shared__ __nv_bfloat16 Qs[64 * FPAD];
    __shared__ __nv_bfloat16 Ksm[64 * FPAD];
    __shared__ __nv_bfloat16 Vsm[64 * FPAD];

    const int qt  = gridDim.x - 1 - blockIdx.x;   // heavy tiles first
    const int h   = blockIdx.y;
    const int b   = blockIdx.z;
    const int tid = threadIdx.x;
    const int wid = tid >> 5, lane = tid & 31;
    const int gid = lane >> 2, tig = lane & 3;
    const int qbase = qt * 64;

    const int srow = tid >> 1, shalf = tid & 1;   // staging: 2 threads per row

    // ---- stage Q (fp32 -> bf16) ----
    {
        const float4* qg = reinterpret_cast<const float4*>(
            QKV + ((size_t)(b * SS + qbase + srow)) * QKVN + h * HDD + shalf * 32);
        uint32_t* qs32 = reinterpret_cast<uint32_t*>(Qs);
        int base = srow * (FPAD / 2) + shalf * 16;
#pragma unroll
        for (int i = 0; i < 8; i++) {
            float4 v = qg[i];
            qs32[base + 2 * i]     = pack_bf16(v.x, v.y);
            qs32[base + 2 * i + 1] = pack_bf16(v.z, v.w);
        }
    }
    __syncthreads();

    // ---- Q fragments (held for whole kernel) ----
    uint32_t qf[4][4];
    {
        const uint32_t qsb = smem_u32(Qs);
        const uint32_t rowQ = (uint32_t)(wid * 16 + (lane & 15));
#pragma unroll
        for (int c = 0; c < 4; c++) {
            uint32_t colQ = (uint32_t)(c * 16 + ((lane & 16) ? 8 : 0));
            ldsm_x4(qf[c][0], qf[c][1], qf[c][2], qf[c][3],
                    qsb + (rowQ * FPAD + colQ) * 2);
        }
    }

    float o[8][4];
#pragma unroll
    for (int nt = 0; nt < 8; nt++)
#pragma unroll
        for (int rr = 0; rr < 4; rr++) o[nt][rr] = 0.0f;
    float m0 = -1e30f, m1 = -1e30f, l0 = 0.0f, l1 = 0.0f;
    const float scale = 0.125f;   // 1/sqrt(64)

    const uint32_t ksb = smem_u32(Ksm);
    const uint32_t vsb = smem_u32(Vsm);

    for (int kt = 0; kt <= qt; kt++) {
        __syncthreads();   // previous tile's reads done before restage
        // ---- stage K and V tiles ----
        {
            const float4* kg = reinterpret_cast<const float4*>(
                QKV + ((size_t)(b * SS + kt * 64 + srow)) * QKVN + DD + h * HDD + shalf * 32);
            const float4* vg = reinterpret_cast<const float4*>(
                QKV + ((size_t)(b * SS + kt * 64 + srow)) * QKVN + 2 * DD + h * HDD + shalf * 32);
            uint32_t* ks32 = reinterpret_cast<uint32_t*>(Ksm);
            uint32_t* vs32 = reinterpret_cast<uint32_t*>(Vsm);
            int base = srow * (FPAD / 2) + shalf * 16;
#pragma unroll
            for (int i = 0; i < 8; i++) {
                float4 v = kg[i];
                ks32[base + 2 * i]     = pack_bf16(v.x, v.y);
                ks32[base + 2 * i + 1] = pack_bf16(v.z, v.w);
                float4 w = vg[i];
                vs32[base + 2 * i]     = pack_bf16(w.x, w.y);
                vs32[base + 2 * i + 1] = pack_bf16(w.z, w.w);
            }
        }
        __syncthreads();

        // ---- scores S = Q @ K^T (bf16 mma, fp32 acc) ----
        float s[8][4];
#pragma unroll
        for (int nt = 0; nt < 8; nt++)
#pragma unroll
            for (int rr = 0; rr < 4; rr++) s[nt][rr] = 0.0f;

#pragma unroll
        for (int p = 0; p < 4; p++) {          // key-16 groups (ntile pair)
            const uint32_t rowK = (uint32_t)(p * 16 + ((lane & 16) ? 8 : 0) + (lane & 7));
#pragma unroll
            for (int c = 0; c < 4; c++) {      // hd-16 chunks
                uint32_t colK = (uint32_t)(c * 16 + ((lane & 8) ? 8 : 0));
                uint32_t k0, k1, k2, k3;
                ldsm_x4(k0, k1, k2, k3, ksb + (rowK * FPAD + colK) * 2);
                mma_bf16(s[2 * p],     qf[c], k0, k1);
                mma_bf16(s[2 * p + 1], qf[c], k2, k3);
            }
        }

        // scale + causal mask (diagonal tile only)
        if (kt == qt) {
            const int row0 = qbase + wid * 16 + gid;
            const int row1 = row0 + 8;
#pragma unroll
            for (int nt = 0; nt < 8; nt++) {
                int col = kt * 64 + nt * 8 + 2 * tig;
                s[nt][0] = (col     > row0) ? -1e30f : s[nt][0] * scale;
                s[nt][1] = (col + 1 > row0) ? -1e30f : s[nt][1] * scale;
                s[nt][2] = (col     > row1) ? -1e30f : s[nt][2] * scale;
                s[nt][3] = (col + 1 > row1) ? -1e30f : s[nt][3] * scale;
            }
        } else {
#pragma unroll
            for (int nt = 0; nt < 8; nt++) {
                s[nt][0] *= scale; s[nt][1] *= scale;
                s[nt][2] *= scale; s[nt][3] *= scale;
            }
        }

        // ---- online softmax ----
        float tm0 = -1e30f, tm1 = -1e30f;
#pragma unroll
        for (int nt = 0; nt < 8; nt++) {
            tm0 = fmaxf(tm0, fmaxf(s[nt][0], s[nt][1]));
            tm1 = fmaxf(tm1, fmaxf(s[nt][2], s[nt][3]));
        }
        tm0 = fmaxf(tm0, __shfl_xor_sync(0xffffffffu, tm0, 1));
        tm0 = fmaxf(tm0, __shfl_xor_sync(0xffffffffu, tm0, 2));
        tm1 = fmaxf(tm1, __shfl_xor_sync(0xffffffffu, tm1, 1));
        tm1 = fmaxf(tm1, __shfl_xor_sync(0xffffffffu, tm1, 2));

        float mn0 = fmaxf(m0, tm0), mn1 = fmaxf(m1, tm1);
        float corr0 = __expf(m0 - mn0), corr1 = __expf(m1 - mn1);
        m0 = mn0; m1 = mn1;

        float ps0 = 0.0f, ps1 = 0.0f;
#pragma unroll
        for (int nt = 0; nt < 8; nt++) {
            s[nt][0] = __expf(s[nt][0] - m0);
            s[nt][1] = __expf(s[nt][1] - m0);
            s[nt][2] = __expf(s[nt][2] - m1);
            s[nt][3] = __expf(s[nt][3] - m1);
            ps0 += s[nt][0] + s[nt][1];
            ps1 += s[nt][2] + s[nt][3];
        }
        ps0 += __shfl_xor_sync(0xffffffffu, ps0, 1);
        ps0 += __shfl_xor_sync(0xffffffffu, ps0, 2);
        ps1 += __shfl_xor_sync(0xffffffffu, ps1, 1);
        ps1 += __shfl_xor_sync(0xffffffffu, ps1, 2);
        l0 = l0 * corr0 + ps0;
        l1 = l1 * corr1 + ps1;

#pragma unroll
        for (int nt = 0; nt < 8; nt++) {
            o[nt][0] *= corr0; o[nt][1] *= corr0;
            o[nt][2] *= corr1; o[nt][3] *= corr1;
        }

        // ---- O += P @ V (P from score frags, V via trans ldmatrix) ----
#pragma unroll
        for (int j = 0; j < 4; j++) {          // key-16 chunks
            uint32_t a[4];
            a[0] = pack_bf16(s[2 * j][0],     s[2 * j][1]);
            a[1] = pack_bf16(s[2 * j][2],     s[2 * j][3]);
            a[2] = pack_bf16(s[2 * j + 1][0], s[2 * j + 1][1]);
            a[3] = pack_bf16(s[2 * j + 1][2], s[2 * j + 1][3]);
            const uint32_t rowV = (uint32_t)(j * 16 + ((lane & 8) ? 8 : 0) + (lane & 7));
#pragma unroll
            for (int g = 0; g < 4; g++) {      // hd-16 groups (ntile pair)
                uint32_t colV = (uint32_t)(g * 16 + ((lane & 16) ? 8 : 0));
                uint32_t v0, v1, v2, v3;
                ldsm_x4_t(v0, v1, v2, v3, vsb + (rowV * FPAD + colV) * 2);
                mma_bf16(o[2 * g],     a, v0, v1);
                mma_bf16(o[2 * g + 1], a, v2, v3);
            }
        }
    }

    // ---- finalize + write ----
    float inv0 = 1.0f / l0, inv1 = 1.0f / l1;
    float* orow = O + (size_t)(b * SS + qbase + wid * 16 + gid) * DD + h * HDD;
#pragma unroll
    for (int nt = 0; nt < 8; nt++) {
        int col = nt * 8 + 2 * tig;
        *reinterpret_cast<float2*>(orow + col) =
            make_float2(o[nt][0] * inv0, o[nt][1] * inv0);
        *reinterpret_cast<float2*>(orow + 8 * DD + col) =
            make_float2(o[nt][2] * inv1, o[nt][3] * inv1);
    }
}

// ---------------- LayerNorm ----------------
__global__ __launch_bounds__(256)
void ln_kernel(const float* __restrict__ in, const float* __restrict__ gamma,
               const float* __restrict__ beta, float* __restrict__ out) {
    __shared__ float red1[8];
    __shared__ float red2[8];
    const int row = blockIdx.x;
    const int tid = threadIdx.x;
    float4 v = reinterpret_cast<const float4*>(in + (size_t)row * DD)[tid];

    float s = v.x + v.y + v.z + v.w;
#pragma unroll
    for (int o = 16; o > 0; o >>= 1) s += __shfl_xor_sync(0xffffffffu, s, o);
    if ((tid & 31) == 0) red1[tid >> 5] = s;
    __syncthreads();
    float mean = (red1[0]+red1[1]+red1[2]+red1[3]+red1[4]+red1[5]+red1[6]+red1[7])
                 * (1.0f / 1024.0f);

    float dx = v.x - mean, dy = v.y - mean, dz = v.z - mean, dw = v.w - mean;
    float sq = dx*dx + dy*dy + dz*dz + dw*dw;
#pragma unroll
    for (int o = 16; o > 0; o >>= 1) sq += __shfl_xor_sync(0xffffffffu, sq, o);
    if ((tid & 31) == 0) red2[tid >> 5] = sq;
    __syncthreads();
    float var = (red2[0]+red2[1]+red2[2]+red2[3]+red2[4]+red2[5]+red2[6]+red2[7])
                * (1.0f / 1024.0f);
    float r = rsqrtf(var + 1e-5f);

    float4 g4 = reinterpret_cast<const float4*>(gamma)[tid];
    float4 b4 = reinterpret_cast<const float4*>(beta)[tid];
    float4 o4;
    o4.x = dx * r * g4.x + b4.x;
    o4.y = dy * r * g4.y + b4.y;
    o4.z = dz * r * g4.z + b4.z;
    o4.w = dw * r * g4.w + b4.w;
    reinterpret_cast<float4*>(out + (size_t)row * DD)[tid] = o4;
}

// ---------------- launch ----------------
extern "C" void kernel_launch(void* const* d_in, const int* in_sizes, int n_in,
                              void* d_out, int out_size) {
    const float* x     = (const float*)d_in[0];
    const float* Wq    = (const float*)d_in[1];
    const float* bq    = (const float*)d_in[2];
    const float* Wk    = (const float*)d_in[3];
    const float* bk    = (const float*)d_in[4];
    const float* Wv    = (const float*)d_in[5];
    const float* bv    = (const float*)d_in[6];
    const float* Wp    = (const float*)d_in[7];
    const float* bp    = (const float*)d_in[8];
    const float* g0    = (const float*)d_in[9];
    const float* beta0 = (const float*)d_in[10];
    const float* W1    = (const float*)d_in[11];
    const float* b1    = (const float*)d_in[12];
    const float* W2    = (const float*)d_in[13];
    const float* b2    = (const float*)d_in[14];
    const float* g1    = (const float*)d_in[15];
    const float* beta1 = (const float*)d_in[16];
    float* out = (float*)d_out;

    float *wt, *qkv, *y, *x1, *hbuf, *mbuf, *x2, *bqkv;
    cudaGetSymbolAddress((void**)&wt,   g_wt);
    cudaGetSymbolAddress((void**)&qkv,  g_qkv);
    cudaGetSymbolAddress((void**)&y,    g_y);
    cudaGetSymbolAddress((void**)&x1,   g_x1);
    cudaGetSymbolAddress((void**)&hbuf, g_h);
    cudaGetSymbolAddress((void**)&mbuf, g_m);
    cudaGetSymbolAddress((void**)&x2,   g_x2);
    cudaGetSymbolAddress((void**)&bqkv, g_bqkv);

    float* WtQKV = wt;                       // [3072][1024]
    float* WtP   = wt + 3u*1024u*1024u;      // [1024][1024]
    float* WtM1  = wt + 4u*1024u*1024u;      // [4096][1024]
    float* WtM2  = wt + 8u*1024u*1024u;      // [1024][4096]

    // smem sizes: stage = A(18432) + B(NB*36*4)
    const int SMT256 = 1024 + 3 * (18432 + 256 * 36 * 4);  // 166912... (A+B)=55296*3+1024
    const int SMT128 = 1024 + 3 * (18432 + 128 * 36 * 4);  // 111616
    cudaFuncSetAttribute(tc_gemm<0,256>, cudaFuncAttributeMaxDynamicSharedMemorySize, SMT256);
    cudaFuncSetAttribute(tc_gemm<1,256>, cudaFuncAttributeMaxDynamicSharedMemorySize, SMT256);
    cudaFuncSetAttribute(tc_gemm<2,128>, cudaFuncAttributeMaxDynamicSharedMemorySize, SMT128);

    // prep
    transpose_rna_kernel<<<dim3(32, 32),  256>>>(Wq, WtQKV,                 DD, DD);
    transpose_rna_kernel<<<dim3(32, 32),  256>>>(Wk, WtQKV + 1024u*1024u,   DD, DD);
    transpose_rna_kernel<<<dim3(32, 32),  256>>>(Wv, WtQKV + 2u*1024u*1024u,DD, DD);
    transpose_rna_kernel<<<dim3(32, 32),  256>>>(Wp, WtP,                   DD, DD);
    transpose_rna_kernel<<<dim3(128, 32), 256>>>(W1, WtM1,                  DD, FF);
    transpose_rna_kernel<<<dim3(32, 128), 256>>>(W2, WtM2,                  FF, DD);
    concat_bias_kernel<<<3, 1024>>>(bq, bk, bv, bqkv);

    // qkv = x @ [Wq|Wk|Wv] + bqkv
    tc_gemm<0,256><<<dim3(QKVN/256, MM/128), 256, SMT256>>>(x, WtQKV, bqkv, nullptr, qkv, MM, QKVN, DD);

    // causal attention (tensor-core flash)
    flash_kernel<<<dim3(SS / 64, HH, BB), 128>>>(qkv, y);

    // x1 = y@Wp + bp + x
    tc_gemm<2,128><<<dim3(DD/128, MM/128), 256, SMT128>>>(y, WtP, bp, x, x1, MM, DD, DD);

    // LN0
    ln_kernel<<<MM, 256>>>(x1, g0, beta0, hbuf);

    // MLP
    tc_gemm<1,256><<<dim3(FF/256, MM/128), 256, SMT256>>>(hbuf, WtM1, b1, nullptr, mbuf, MM, FF, DD);
    tc_gemm<2,128><<<dim3(DD/128, MM/128), 256, SMT128>>>(mbuf, WtM2, b2, x1, x2, MM, DD, FF);

    // LN1 -> output
    ln_kernel<<<MM, 256>>>(x2, g1, beta1, out);
}

// round 6
// speedup vs baseline: 4.2402x; 1.2215x over previous
#include <cuda_runtime.h>
#include <cuda_bf16.h>
#include <math.h>
#include <cstdint>

// Problem constants
#define BB 2
#define SS 2048
#define DD 1024
#define HH 16
#define HDD 64
#define MM (BB*SS)          // 4096 rows
#define FF (4*DD)           // 4096 mlp hidden
#define QKVN 3072

// ---------------- scratch (device globals; no allocation allowed) ----------------
__device__ float g_wt [12u*1024u*1024u];             // transposed+rounded weights
__device__ __nv_bfloat16 g_qkv[(size_t)MM*QKVN];     // fused q|k|v (bf16)
__device__ float g_y  [MM*DD];
__device__ float g_x1 [MM*DD];
__device__ float g_h  [MM*DD];
__device__ float g_m  [(size_t)MM*FF];
__device__ float g_x2 [MM*DD];
__device__ float g_bqkv[QKVN];

// ---------------- helpers ----------------
__device__ __forceinline__ uint32_t smem_u32(const void* p) {
    uint32_t a;
    asm("{ .reg .u64 t; cvta.to.shared.u64 t, %1; cvt.u32.u64 %0, t; }" : "=r"(a) : "l"(p));
    return a;
}
__device__ __forceinline__ uint32_t f2tf32(float x) {
    uint32_t u;
    asm("cvt.rna.tf32.f32 %0, %1;" : "=r"(u) : "f"(x));
    return u;
}
__device__ __forceinline__ uint32_t pack_bf16(float lo, float hi) {
    uint32_t d;
    asm("cvt.rn.bf16x2.f32 %0, %1, %2;" : "=r"(d) : "f"(hi), "f"(lo));
    return d;
}
__device__ __forceinline__ float gelu_tanh_f(float x) {
    float x3 = x * x * x;
    float t = tanhf(0.7978845608028654f * (x + 0.044715f * x3));
    return 0.5f * x * (1.0f + t);
}

#define CP_ASYNC16(dst, src) \
    asm volatile("cp.async.cg.shared.global [%0], [%1], 16;" :: "r"(dst), "l"(src))
#define CP_COMMIT() asm volatile("cp.async.commit_group;" ::: "memory")
#define CP_WAIT2()  asm volatile("cp.async.wait_group 2;" ::: "memory")
#define CP_WAIT1()  asm volatile("cp.async.wait_group 1;" ::: "memory")

__device__ __forceinline__ void mma_tf32(float* c, const uint32_t* a, const uint32_t* b) {
    asm volatile(
        "mma.sync.aligned.m16n8k8.row.col.f32.tf32.tf32.f32 "
        "{%0,%1,%2,%3}, {%4,%5,%6,%7}, {%8,%9}, {%0,%1,%2,%3};"
        : "+f"(c[0]), "+f"(c[1]), "+f"(c[2]), "+f"(c[3])
        : "r"(a[0]), "r"(a[1]), "r"(a[2]), "r"(a[3]), "r"(b[0]), "r"(b[1]));
}
__device__ __forceinline__ void mma_bf16(float* c, const uint32_t* a, uint32_t b0, uint32_t b1) {
    asm volatile(
        "mma.sync.aligned.m16n8k16.row.col.f32.bf16.bf16.f32 "
        "{%0,%1,%2,%3}, {%4,%5,%6,%7}, {%8,%9}, {%0,%1,%2,%3};"
        : "+f"(c[0]), "+f"(c[1]), "+f"(c[2]), "+f"(c[3])
        : "r"(a[0]), "r"(a[1]), "r"(a[2]), "r"(a[3]), "r"(b0), "r"(b1));
}
__device__ __forceinline__ void ldsm_x4(uint32_t& r0, uint32_t& r1, uint32_t& r2, uint32_t& r3,
                                        uint32_t addr) {
    asm volatile("ldmatrix.sync.aligned.m8n8.x4.shared.b16 {%0,%1,%2,%3}, [%4];"
        : "=r"(r0), "=r"(r1), "=r"(r2), "=r"(r3) : "r"(addr));
}
__device__ __forceinline__ void ldsm_x4_t(uint32_t& r0, uint32_t& r1, uint32_t& r2, uint32_t& r3,
                                          uint32_t addr) {
    asm volatile("ldmatrix.sync.aligned.m8n8.x4.trans.shared.b16 {%0,%1,%2,%3}, [%4];"
        : "=r"(r0), "=r"(r1), "=r"(r2), "=r"(r3) : "r"(addr));
}

// ---------------- prep: transpose + tf32-round weights ----------------
__global__ __launch_bounds__(256)
void transpose_rna_kernel(const float* __restrict__ in, float* __restrict__ out, int K, int N) {
    __shared__ float t[32][33];
    int n0 = blockIdx.x * 32, k0 = blockIdx.y * 32;
    int tx = threadIdx.x & 31, ty = threadIdx.x >> 5;
#pragma unroll
    for (int i = 0; i < 4; i++)
        t[ty + i * 8][tx] = in[(size_t)(k0 + ty + i * 8) * N + n0 + tx];
    __syncthreads();
#pragma unroll
    for (int i = 0; i < 4; i++)
        out[(size_t)(n0 + ty + i * 8) * K + k0 + tx] =
            __uint_as_float(f2tf32(t[tx][ty + i * 8]));
}

__global__ void concat_bias_kernel(const float* bq, const float* bk, const float* bv, float* o) {
    int c = threadIdx.x;
    o[blockIdx.x * 1024 + c] =
        (blockIdx.x == 0) ? bq[c] : (blockIdx.x == 1) ? bk[c] : bv[c];
}

// ---------------- tf32 mma.sync GEMM with ldmatrix fragments ----------------
// C[M,N] = A[M,K] @ Wt[N,K]^T + bias (+epi)
// EPI: 0=bias, 1=bias+GELU, 2=bias+residual.  OB: 0=f32 out, 1=bf16 out.
#define GBM 128
#define GBK 32
#define APAD 36
#define NSTG 3
#define SM_STAGES 1024
#define GNB 256

template <int EPI, int OB>
__global__ __launch_bounds__(256, 1)
void tc_gemm(const float* __restrict__ A, const float* __restrict__ Wt,
             const float* __restrict__ bias, const float* __restrict__ R,
             void* __restrict__ Cv, int M, int N, int K) {
    constexpr int NB = GNB;
    constexpr int WN = NB / 4;                 // 64
    constexpr int NT = WN / 8;                 // 8
    constexpr int NP = WN / 16;                // 4
    constexpr int ATB = GBM * APAD * 4;        // 18432
    constexpr int BTB = NB * APAD * 4;         // 36864
    constexpr int STGB = ATB + BTB;

    extern __shared__ char smem[];
    const uint32_t sb = smem_u32(smem);
    const int tid  = threadIdx.x;
    const int wid  = tid >> 5, lane = tid & 31;
    const int warpM = wid >> 2;
    const int warpN = wid & 3;
    const int gid = lane >> 2;
    const int tig = lane & 3;
    const int rowBase = blockIdx.y * GBM;
    const int colBase = blockIdx.x * NB;

    const uint32_t aoff_l = ((uint32_t)(warpM * 64 + (lane & 15)) * APAD +
                             ((lane & 16) ? 4u : 0u)) * 4u;
    const uint32_t boff_l = ((uint32_t)(warpN * WN + ((lane & 16) ? 8 : 0) + (lane & 7)) * APAD +
                             ((lane & 8) ? 4u : 0u)) * 4u;

    if (tid < NB / 4)
        *reinterpret_cast<float4*>(smem + tid * 16) =
            *reinterpret_cast<const float4*>(bias + colBase + tid * 4);

    const float* Abase = A  + (size_t)rowBase * K;
    const float* Bbase = Wt + (size_t)colBase * K;
    const int nch = K >> 5;

#pragma unroll
    for (int s = 0; s < NSTG; s++) {
        if (s < nch) {
            const uint32_t st = sb + SM_STAGES + s * STGB;
#pragma unroll
            for (int i = 0; i < 4; i++) {
                int u = tid + i * 256;
                int r = u >> 3, c4 = u & 7;
                CP_ASYNC16(st + (uint32_t)(r * APAD + c4 * 4) * 4,
                           Abase + (size_t)r * K + s * GBK + c4 * 4);
            }
#pragma unroll
            for (int i = 0; i < NB / 32; i++) {
                int u = tid + i * 256;
                int r = u >> 3, c4 = u & 7;
                CP_ASYNC16(st + ATB + (uint32_t)(r * APAD + c4 * 4) * 4,
                           Bbase + (size_t)r * K + s * GBK + c4 * 4);
            }
        }
        CP_COMMIT();
    }

    float acc[4][NT][4];
#pragma unroll
    for (int mt = 0; mt < 4; mt++)
#pragma unroll
        for (int nt = 0; nt < NT; nt++)
#pragma unroll
            for (int rr = 0; rr < 4; rr++) acc[mt][nt][rr] = 0.0f;

    for (int c = 0; c < nch; c++) {
        CP_WAIT2();
        __syncthreads();
        const int slot = c % NSTG;
        const uint32_t abase = sb + SM_STAGES + slot * STGB + aoff_l;
        const uint32_t bbase = sb + SM_STAGES + slot * STGB + ATB + boff_l;

#pragma unroll
        for (int ks = 0; ks < 4; ks++) {
            const uint32_t kb = (uint32_t)(ks * 32);
            uint32_t a[4][4], b[NT][2];
#pragma unroll
            for (int mt = 0; mt < 4; mt++)
                ldsm_x4(a[mt][0], a[mt][1], a[mt][2], a[mt][3],
                        abase + (uint32_t)(mt * 16 * APAD * 4) + kb);
#pragma unroll
            for (int p = 0; p < NP; p++)
                ldsm_x4(b[2*p][0], b[2*p][1], b[2*p+1][0], b[2*p+1][1],
                        bbase + (uint32_t)(p * 16 * APAD * 4) + kb);
#pragma unroll
            for (int mt = 0; mt < 4; mt++)
#pragma unroll
                for (int nt = 0; nt < NT; nt++)
                    mma_tf32(acc[mt][nt], a[mt], b[nt]);
        }
        __syncthreads();

        if (c + NSTG < nch) {
            const uint32_t st = sb + SM_STAGES + slot * STGB;
            const int cc = c + NSTG;
#pragma unroll
            for (int i = 0; i < 4; i++) {
                int u = tid + i * 256;
                int r = u >> 3, c4 = u & 7;
                CP_ASYNC16(st + (uint32_t)(r * APAD + c4 * 4) * 4,
                           Abase + (size_t)r * K + cc * GBK + c4 * 4);
            }
#pragma unroll
            for (int i = 0; i < NB / 32; i++) {
                int u = tid + i * 256;
                int r = u >> 3, c4 = u & 7;
                CP_ASYNC16(st + ATB + (uint32_t)(r * APAD + c4 * 4) * 4,
                           Bbase + (size_t)r * K + cc * GBK + c4 * 4);
            }
        }
        CP_COMMIT();
    }

    // epilogue
    const float* bs = reinterpret_cast<const float*>(smem);
#pragma unroll
    for (int mt = 0; mt < 4; mt++) {
        int r0 = rowBase + warpM * 64 + mt * 16 + gid;
#pragma unroll
        for (int nt = 0; nt < NT; nt++) {
            int colL = warpN * WN + nt * 8 + 2 * tig;
            int col  = colBase + colL;
            float b0 = bs[colL], b1 = bs[colL + 1];
            float2 o0 = make_float2(acc[mt][nt][0] + b0, acc[mt][nt][1] + b1);
            float2 o1 = make_float2(acc[mt][nt][2] + b0, acc[mt][nt][3] + b1);
            if (EPI == 1) {
                o0.x = gelu_tanh_f(o0.x); o0.y = gelu_tanh_f(o0.y);
                o1.x = gelu_tanh_f(o1.x); o1.y = gelu_tanh_f(o1.y);
            }
            if (EPI == 2) {
                float2 r0v = *reinterpret_cast<const float2*>(R + (size_t)r0 * N + col);
                float2 r1v = *reinterpret_cast<const float2*>(R + (size_t)(r0 + 8) * N + col);
                o0.x += r0v.x; o0.y += r0v.y;
                o1.x += r1v.x; o1.y += r1v.y;
            }
            if (OB == 0) {
                float* C = reinterpret_cast<float*>(Cv);
                *reinterpret_cast<float2*>(C + (size_t)r0 * N + col) = o0;
                *reinterpret_cast<float2*>(C + (size_t)(r0 + 8) * N + col) = o1;
            } else {
                __nv_bfloat16* C = reinterpret_cast<__nv_bfloat16*>(Cv);
                *reinterpret_cast<uint32_t*>(C + (size_t)r0 * N + col) = pack_bf16(o0.x, o0.y);
                *reinterpret_cast<uint32_t*>(C + (size_t)(r0 + 8) * N + col) = pack_bf16(o1.x, o1.y);
            }
        }
    }
}

// ---------------- tensor-core flash attention (bf16 in gmem, cp.async pipeline) ----------------
// CTA: 256 threads (8 warps x 16 q-rows = 128 q-rows). K/V tiles of 64 keys, double buffered.
#define FPAD 72
#define FQ_ELE (128 * FPAD)
#define FKV_ELE (64 * FPAD)
#define FSMEM ((FQ_ELE + 4 * FKV_ELE) * 2)     // 55296 bytes

__global__ __launch_bounds__(256)
void flash_kernel(const __nv_bfloat16* __restrict__ QKV, float* __restrict__ O) {
    extern __shared__ char fsm[];
    const uint32_t sq = smem_u32(fsm);                       // Q
    const uint32_t sk0 = sq + FQ_ELE * 2;                    // K buf0
    const uint32_t sv0 = sk0 + 2 * FKV_ELE * 2;              // V buf0 (after K bufs)

    const int qt  = gridDim.x - 1 - blockIdx.x;   // heavy tiles first
    const int h   = blockIdx.y;
    const int b   = blockIdx.z;
    const int tid = threadIdx.x;
    const int wid = tid >> 5, lane = tid & 31;
    const int gid = lane >> 2, tig = lane & 3;
    const int qbase = qt * 128;
    const int nkt = 2 * (qt + 1);

    const __nv_bfloat16* qg = QKV + ((size_t)(b * SS + qbase)) * QKVN + h * HDD;
    const __nv_bfloat16* kg = QKV + ((size_t)(b * SS)) * QKVN + DD + h * HDD;
    const __nv_bfloat16* vg = QKV + ((size_t)(b * SS)) * QKVN + 2 * DD + h * HDD;

    // ---- prologue: Q (group 0), KV tile 0 (group 1), KV tile 1 (group 2) ----
#pragma unroll
    for (int i = 0; i < 4; i++) {
        int u = tid + i * 256;
        int r = u >> 3, c = u & 7;
        CP_ASYNC16(sq + (uint32_t)(r * FPAD + c * 8) * 2, qg + (size_t)r * QKVN + c * 8);
    }
    CP_COMMIT();
#pragma unroll
    for (int s = 0; s < 2; s++) {
#pragma unroll
        for (int i = 0; i < 2; i++) {
            int u = tid + i * 256;
            int r = u >> 3, c = u & 7;
            uint32_t off = (uint32_t)(r * FPAD + c * 8) * 2 + (uint32_t)(s * FKV_ELE * 2);
            CP_ASYNC16(sk0 + off, kg + (size_t)(s * 64 + r) * QKVN + c * 8);
            CP_ASYNC16(sv0 + off, vg + (size_t)(s * 64 + r) * QKVN + c * 8);
        }
        CP_COMMIT();
    }
    CP_WAIT1();            // Q + KV0 complete
    __syncthreads();

    // ---- Q fragments ----
    uint32_t qf[4][4];
    {
        const uint32_t rowQ = (uint32_t)(wid * 16 + (lane & 15));
#pragma unroll
        for (int c = 0; c < 4; c++) {
            uint32_t colQ = (uint32_t)(c * 16 + ((lane & 16) ? 8 : 0));
            ldsm_x4(qf[c][0], qf[c][1], qf[c][2], qf[c][3],
                    sq + (rowQ * FPAD + colQ) * 2);
        }
    }

    float o[8][4];
#pragma unroll
    for (int nt = 0; nt < 8; nt++)
#pragma unroll
        for (int rr = 0; rr < 4; rr++) o[nt][rr] = 0.0f;
    float m0 = -1e30f, m1 = -1e30f, l0 = 0.0f, l1 = 0.0f;
    const float scale = 0.125f;
    const int rowW = qbase + wid * 16;           // warp's min row

    for (int kt = 0; kt < nkt; kt++) {
        const int buf = kt & 1;
        const uint32_t ksb = sk0 + (uint32_t)(buf * FKV_ELE * 2);
        const uint32_t vsb = sv0 + (uint32_t)(buf * FKV_ELE * 2);

        // skip warp-tiles that are fully masked (all keys above the causal line)
        if (kt * 64 <= rowW + 15) {
            // ---- S = Q @ K^T ----
            float s[8][4];
#pragma unroll
            for (int nt = 0; nt < 8; nt++)
#pragma unroll
                for (int rr = 0; rr < 4; rr++) s[nt][rr] = 0.0f;
#pragma unroll
            for (int p = 0; p < 4; p++) {
                const uint32_t rowK = (uint32_t)(p * 16 + ((lane & 16) ? 8 : 0) + (lane & 7));
#pragma unroll
                for (int c = 0; c < 4; c++) {
                    uint32_t colK = (uint32_t)(c * 16 + ((lane & 8) ? 8 : 0));
                    uint32_t k0, k1, k2, k3;
                    ldsm_x4(k0, k1, k2, k3, ksb + (rowK * FPAD + colK) * 2);
                    mma_bf16(s[2 * p],     qf[c], k0, k1);
                    mma_bf16(s[2 * p + 1], qf[c], k2, k3);
                }
            }

            // scale + mask (only tiles crossing the causal line)
            if (kt * 64 + 63 > rowW) {
                const int row0 = rowW + gid;
                const int row1 = row0 + 8;
#pragma unroll
                for (int nt = 0; nt < 8; nt++) {
                    int col = kt * 64 + nt * 8 + 2 * tig;
                    s[nt][0] = (col     > row0) ? -1e30f : s[nt][0] * scale;
                    s[nt][1] = (col + 1 > row0) ? -1e30f : s[nt][1] * scale;
                    s[nt][2] = (col     > row1) ? -1e30f : s[nt][2] * scale;
                    s[nt][3] = (col + 1 > row1) ? -1e30f : s[nt][3] * scale;
                }
            } else {
#pragma unroll
                for (int nt = 0; nt < 8; nt++) {
                    s[nt][0] *= scale; s[nt][1] *= scale;
                    s[nt][2] *= scale; s[nt][3] *= scale;
                }
            }

            // ---- online softmax ----
            float tm0 = -1e30f, tm1 = -1e30f;
#pragma unroll
            for (int nt = 0; nt < 8; nt++) {
                tm0 = fmaxf(tm0, fmaxf(s[nt][0], s[nt][1]));
                tm1 = fmaxf(tm1, fmaxf(s[nt][2], s[nt][3]));
            }
            tm0 = fmaxf(tm0, __shfl_xor_sync(0xffffffffu, tm0, 1));
            tm0 = fmaxf(tm0, __shfl_xor_sync(0xffffffffu, tm0, 2));
            tm1 = fmaxf(tm1, __shfl_xor_sync(0xffffffffu, tm1, 1));
            tm1 = fmaxf(tm1, __shfl_xor_sync(0xffffffffu, tm1, 2));

            float mn0 = fmaxf(m0, tm0), mn1 = fmaxf(m1, tm1);
            float corr0 = __expf(m0 - mn0), corr1 = __expf(m1 - mn1);
            m0 = mn0; m1 = mn1;

            float ps0 = 0.0f, ps1 = 0.0f;
#pragma unroll
            for (int nt = 0; nt < 8; nt++) {
                s[nt][0] = __expf(s[nt][0] - m0);
                s[nt][1] = __expf(s[nt][1] - m0);
                s[nt][2] = __expf(s[nt][2] - m1);
                s[nt][3] = __expf(s[nt][3] - m1);
                ps0 += s[nt][0] + s[nt][1];
                ps1 += s[nt][2] + s[nt][3];
            }
            ps0 += __shfl_xor_sync(0xffffffffu, ps0, 1);
            ps0 += __shfl_xor_sync(0xffffffffu, ps0, 2);
            ps1 += __shfl_xor_sync(0xffffffffu, ps1, 1);
            ps1 += __shfl_xor_sync(0xffffffffu, ps1, 2);
            l0 = l0 * corr0 + ps0;
            l1 = l1 * corr1 + ps1;

#pragma unroll
            for (int nt = 0; nt < 8; nt++) {
                o[nt][0] *= corr0; o[nt][1] *= corr0;
                o[nt][2] *= corr1; o[nt][3] *= corr1;
            }

            // ---- O += P @ V ----
#pragma unroll
            for (int j = 0; j < 4; j++) {
                uint32_t a[4];
                a[0] = pack_bf16(s[2 * j][0],     s[2 * j][1]);
                a[1] = pack_bf16(s[2 * j][2],     s[2 * j][3]);
                a[2] = pack_bf16(s[2 * j + 1][0], s[2 * j + 1][1]);
                a[3] = pack_bf16(s[2 * j + 1][2], s[2 * j + 1][3]);
                const uint32_t rowV = (uint32_t)(j * 16 + ((lane & 8) ? 8 : 0) + (lane & 7));
#pragma unroll
                for (int g = 0; g < 4; g++) {
                    uint32_t colV = (uint32_t)(g * 16 + ((lane & 16) ? 8 : 0));
                    uint32_t v0, v1, v2, v3;
                    ldsm_x4_t(v0, v1, v2, v3, vsb + (rowV * FPAD + colV) * 2);
                    mma_bf16(o[2 * g],     a, v0, v1);
                    mma_bf16(o[2 * g + 1], a, v2, v3);
                }
            }
        }

        // ---- pipeline: refill this buffer with tile kt+2, wait for tile kt+1 ----
        if (kt + 1 < nkt) {
            __syncthreads();                       // all reads of buf done
            if (kt + 2 < nkt) {
#pragma unroll
                for (int i = 0; i < 2; i++) {
                    int u = tid + i * 256;
                    int r = u >> 3, c = u & 7;
                    uint32_t off = (uint32_t)(r * FPAD + c * 8) * 2 + (uint32_t)(buf * FKV_ELE * 2);
                    CP_ASYNC16(sk0 + off, kg + (size_t)((kt + 2) * 64 + r) * QKVN + c * 8);
                    CP_ASYNC16(sv0 + off, vg + (size_t)((kt + 2) * 64 + r) * QKVN + c * 8);
                }
            }
            CP_COMMIT();
            CP_WAIT1();                            // tile kt+1 complete
            __syncthreads();
        }
    }

    // ---- finalize + write ----
    float inv0 = 1.0f / l0, inv1 = 1.0f / l1;
    float* orow = O + (size_t)(b * SS + qbase + wid * 16 + gid) * DD + h * HDD;
#pragma unroll
    for (int nt = 0; nt < 8; nt++) {
        int col = nt * 8 + 2 * tig;
        *reinterpret_cast<float2*>(orow + col) =
            make_float2(o[nt][0] * inv0, o[nt][1] * inv0);
        *reinterpret_cast<float2*>(orow + 8 * DD + col) =
            make_float2(o[nt][2] * inv1, o[nt][3] * inv1);
    }
}

// ---------------- LayerNorm ----------------
__global__ __launch_bounds__(256)
void ln_kernel(const float* __restrict__ in, const float* __restrict__ gamma,
               const float* __restrict__ beta, float* __restrict__ out) {
    __shared__ float red1[8];
    __shared__ float red2[8];
    const int row = blockIdx.x;
    const int tid = threadIdx.x;
    float4 v = reinterpret_cast<const float4*>(in + (size_t)row * DD)[tid];

    float s = v.x + v.y + v.z + v.w;
#pragma unroll
    for (int o = 16; o > 0; o >>= 1) s += __shfl_xor_sync(0xffffffffu, s, o);
    if ((tid & 31) == 0) red1[tid >> 5] = s;
    __syncthreads();
    float mean = (red1[0]+red1[1]+red1[2]+red1[3]+red1[4]+red1[5]+red1[6]+red1[7])
                 * (1.0f / 1024.0f);

    float dx = v.x - mean, dy = v.y - mean, dz = v.z - mean, dw = v.w - mean;
    float sq = dx*dx + dy*dy + dz*dz + dw*dw;
#pragma unroll
    for (int o = 16; o > 0; o >>= 1) sq += __shfl_xor_sync(0xffffffffu, sq, o);
    if ((tid & 31) == 0) red2[tid >> 5] = sq;
    __syncthreads();
    float var = (red2[0]+red2[1]+red2[2]+red2[3]+red2[4]+red2[5]+red2[6]+red2[7])
                * (1.0f / 1024.0f);
    float r = rsqrtf(var + 1e-5f);

    float4 g4 = reinterpret_cast<const float4*>(gamma)[tid];
    float4 b4 = reinterpret_cast<const float4*>(beta)[tid];
    float4 o4;
    o4.x = dx * r * g4.x + b4.x;
    o4.y = dy * r * g4.y + b4.y;
    o4.z = dz * r * g4.z + b4.z;
    o4.w = dw * r * g4.w + b4.w;
    reinterpret_cast<float4*>(out + (size_t)row * DD)[tid] = o4;
}

// ---------------- launch ----------------
extern "C" void kernel_launch(void* const* d_in, const int* in_sizes, int n_in,
                              void* d_out, int out_size) {
    const float* x     = (const float*)d_in[0];
    const float* Wq    = (const float*)d_in[1];
    const float* bq    = (const float*)d_in[2];
    const float* Wk    = (const float*)d_in[3];
    const float* bk    = (const float*)d_in[4];
    const float* Wv    = (const float*)d_in[5];
    const float* bv    = (const float*)d_in[6];
    const float* Wp    = (const float*)d_in[7];
    const float* bp    = (const float*)d_in[8];
    const float* g0    = (const float*)d_in[9];
    const float* beta0 = (const float*)d_in[10];
    const float* W1    = (const float*)d_in[11];
    const float* b1    = (const float*)d_in[12];
    const float* W2    = (const float*)d_in[13];
    const float* b2    = (const float*)d_in[14];
    const float* g1    = (const float*)d_in[15];
    const float* beta1 = (const float*)d_in[16];
    float* out = (float*)d_out;

    float *wt, *y, *x1, *hbuf, *mbuf, *x2, *bqkv;
    __nv_bfloat16* qkv;
    cudaGetSymbolAddress((void**)&wt,   g_wt);
    cudaGetSymbolAddress((void**)&qkv,  g_qkv);
    cudaGetSymbolAddress((void**)&y,    g_y);
    cudaGetSymbolAddress((void**)&x1,   g_x1);
    cudaGetSymbolAddress((void**)&hbuf, g_h);
    cudaGetSymbolAddress((void**)&mbuf, g_m);
    cudaGetSymbolAddress((void**)&x2,   g_x2);
    cudaGetSymbolAddress((void**)&bqkv, g_bqkv);

    float* WtQKV = wt;                       // [3072][1024]
    float* WtP   = wt + 3u*1024u*1024u;      // [1024][1024]
    float* WtM1  = wt + 4u*1024u*1024u;      // [4096][1024]
    float* WtM2  = wt + 8u*1024u*1024u;      // [1024][4096]

    const int SMT = 1024 + 3 * (18432 + 256 * 36 * 4);   // 166912
    cudaFuncSetAttribute(tc_gemm<0,1>, cudaFuncAttributeMaxDynamicSharedMemorySize, SMT);
    cudaFuncSetAttribute(tc_gemm<1,0>, cudaFuncAttributeMaxDynamicSharedMemorySize, SMT);
    cudaFuncSetAttribute(tc_gemm<2,0>, cudaFuncAttributeMaxDynamicSharedMemorySize, SMT);
    cudaFuncSetAttribute(flash_kernel, cudaFuncAttributeMaxDynamicSharedMemorySize, FSMEM);

    // prep
    transpose_rna_kernel<<<dim3(32, 32),  256>>>(Wq, WtQKV,                 DD, DD);
    transpose_rna_kernel<<<dim3(32, 32),  256>>>(Wk, WtQKV + 1024u*1024u,   DD, DD);
    transpose_rna_kernel<<<dim3(32, 32),  256>>>(Wv, WtQKV + 2u*1024u*1024u,DD, DD);
    transpose_rna_kernel<<<dim3(32, 32),  256>>>(Wp, WtP,                   DD, DD);
    transpose_rna_kernel<<<dim3(128, 32), 256>>>(W1, WtM1,                  DD, FF);
    transpose_rna_kernel<<<dim3(32, 128), 256>>>(W2, WtM2,                  FF, DD);
    concat_bias_kernel<<<3, 1024>>>(bq, bk, bv, bqkv);

    // qkv = x @ [Wq|Wk|Wv] + bqkv  (bf16 out)
    tc_gemm<0,1><<<dim3(QKVN/256, MM/128), 256, SMT>>>(x, WtQKV, bqkv, nullptr, qkv, MM, QKVN, DD);

    // causal attention (bf16 tensor-core flash, cp.async pipelined)
    flash_kernel<<<dim3(SS / 128, HH, BB), 256, FSMEM>>>(qkv, y);

    // x1 = y@Wp + bp + x
    tc_gemm<2,0><<<dim3(DD/256, MM/128), 256, SMT>>>(y, WtP, bp, x, x1, MM, DD, DD);

    // LN0
    ln_kernel<<<MM, 256>>>(x1, g0, beta0, hbuf);

    // MLP
    tc_gemm<1,0><<<dim3(FF/256, MM/128), 256, SMT>>>(hbuf, WtM1, b1, nullptr, mbuf, MM, FF, DD);
    tc_gemm<2,0><<<dim3(DD/256, MM/128), 256, SMT>>>(mbuf, WtM2, b2, x1, x2, MM, DD, FF);

    // LN1 -> output
    ln_kernel<<<MM, 256>>>(x2, g1, beta1, out);
}